// round 10
// baseline (speedup 1.0000x reference)
#include <cuda_runtime.h>
#include <cuda_bf16.h>
#include <math.h>
#include <stdint.h>

// Problem constants
#define B    128
#define S    400
#define T    50
#define H    512
#define E    128
#define V    50000
#define PADN 1000
#define J3H  1536
#define CB   1537
#define VP   51000

// ---- output layout (flattened tuple, float32) ----
#define PF_OFF  ((size_t)0)
#define PG_OFF  (PF_OFF + (size_t)B*VP)
#define PV_OFF  (PG_OFF + (size_t)B)
#define AD_OFF  (PV_OFF + (size_t)B*V)
#define DH_OFF  (AD_OFF + (size_t)B*S)
#define HH_OFF  (DH_OFF + (size_t)B*(T+1)*H)
#define NPA_OFF (HH_OFF + (size_t)B*H)

// ---- device scratch ----
__device__ __align__(16) float g_gx[B * J3H];
__device__ __align__(16) float g_gh[B * J3H];
__device__ __align__(16) float g_h[B * H];
__device__ __align__(16) float g_hw[B * H];
__device__ __align__(16) float g_hwd[B * H];
__device__ __align__(16) float g_att_scores[B * S];
__device__ __align__(16) float g_ectx[B * H];
__device__ __align__(16) float g_dctx[B * H];
__device__ __align__(16) float g_logits[(size_t)B * V];   // exp(logits)
__device__ __align__(16) float g_sumexp[B];
// pre-split bf16 operands for the vocab GEMM
__device__ __align__(16) unsigned short g_Wvhi[(size_t)V * E];
__device__ __align__(16) unsigned short g_Wvlo[(size_t)V * E];
__device__ __align__(16) unsigned short g_xhi[B * E];
__device__ __align__(16) unsigned short g_xlo[B * E];

// ---- mma machinery (bf16 3-term split) ----
#define TSTR  132
#define TILEB (128 * TSTR * 2)
#define AHI_O 0
#define ALO_O (TILEB)
#define BHI_O (2 * TILEB)
#define BLO_O (3 * TILEB)
#define MMA_DSMEM (4 * TILEB)

__device__ __forceinline__ void split2(float a, float b, uint32_t& hv, uint32_t& lv) {
    __nv_bfloat162 hi = __float22bfloat162_rn(make_float2(a, b));
    float ra = a - __bfloat162float(hi.x);
    float rb = b - __bfloat162float(hi.y);
    __nv_bfloat162 lo = __float22bfloat162_rn(make_float2(ra, rb));
    hv = *reinterpret_cast<uint32_t*>(&hi);
    lv = *reinterpret_cast<uint32_t*>(&lo);
}
__device__ __forceinline__ void mma16816(float* c, const uint32_t* a, const uint32_t* b) {
    asm volatile(
        "mma.sync.aligned.m16n8k16.row.col.f32.bf16.bf16.f32 "
        "{%0,%1,%2,%3}, {%4,%5,%6,%7}, {%8,%9}, {%0,%1,%2,%3};"
        : "+f"(c[0]), "+f"(c[1]), "+f"(c[2]), "+f"(c[3])
        : "r"(a[0]), "r"(a[1]), "r"(a[2]), "r"(a[3]), "r"(b[0]), "r"(b[1]));
}
__device__ __forceinline__ void mma_chunk(char* smc, int wm, int wn, int g, int t,
                                          float acc[2][4][4]) {
#pragma unroll
    for (int term = 0; term < 3; term++) {
        int aoff = (term == 2) ? ALO_O : AHI_O;
        int boff = (term == 1) ? BLO_O : BHI_O;
#pragma unroll
        for (int ks = 0; ks < 8; ks++) {
            int kb = ks * 16;
            uint32_t af[2][4], bf[4][2];
#pragma unroll
            for (int mi = 0; mi < 2; mi++) {
                int row = wm * 32 + mi * 16 + g;
                size_t o = (size_t)aoff + (size_t)(row * TSTR + kb + 2 * t) * 2;
                af[mi][0] = *reinterpret_cast<const uint32_t*>(smc + o);
                af[mi][1] = *reinterpret_cast<const uint32_t*>(smc + o + 8 * TSTR * 2);
                af[mi][2] = *reinterpret_cast<const uint32_t*>(smc + o + 16);
                af[mi][3] = *reinterpret_cast<const uint32_t*>(smc + o + 8 * TSTR * 2 + 16);
            }
#pragma unroll
            for (int ni = 0; ni < 4; ni++) {
                int row = wn * 32 + ni * 8 + g;
                size_t o = (size_t)boff + (size_t)(row * TSTR + kb + 2 * t) * 2;
                bf[ni][0] = *reinterpret_cast<const uint32_t*>(smc + o);
                bf[ni][1] = *reinterpret_cast<const uint32_t*>(smc + o + 16);
            }
#pragma unroll
            for (int mi = 0; mi < 2; mi++)
#pragma unroll
                for (int ni = 0; ni < 4; ni++)
                    mma16816(acc[mi][ni], af[mi], bf[ni]);
        }
    }
}

// ============================================================
// K_convW (side stream, input-only dep): split outv_W -> bf16 hi/lo
// V*E = 6.4M floats; 6250 blocks x 256 threads x 4 floats.
// ============================================================
__global__ void k_convW(const float* __restrict__ Wv) {
    size_t i = ((size_t)blockIdx.x * 256 + threadIdx.x) * 4;
    float4 w = *reinterpret_cast<const float4*>(Wv + i);
    uint32_t h0, l0, h1, l1;
    split2(w.x, w.y, h0, l0);
    split2(w.z, w.w, h1, l1);
    *reinterpret_cast<uint2*>(g_Wvhi + i) = make_uint2(h0, h1);
    *reinterpret_cast<uint2*>(g_Wvlo + i) = make_uint2(l0, l1);
}

// ============================================================
// K1: fused GRU GEMMs, smem-tiled (R4-proven fp32)
// ============================================================
__global__ void __launch_bounds__(256) k_grugemm(const float* __restrict__ Wih,
                                                 const float* __restrict__ Whh,
                                                 const int* __restrict__ tok,
                                                 const float* __restrict__ emb,
                                                 const float* __restrict__ lh) {
    int z = blockIdx.z;
    const float* W = z ? Whh : Wih;
    float* Cdst    = z ? g_gh : g_gx;
    int K = z ? H : E;

    __shared__ float Ws[128][33];
    __shared__ float Xs[32][17];
    __shared__ int stok[16];
    int tid = threadIdx.x;
    int j0 = blockIdx.x * 128, b0 = blockIdx.y * 16;
    if (tid < 16) stok[tid] = tok[b0 + tid];
    int tj = tid & 31, tb = tid >> 5;
    float acc[4][2];
#pragma unroll
    for (int q = 0; q < 4; q++) { acc[q][0] = 0.f; acc[q][1] = 0.f; }

    for (int kc = 0; kc < K; kc += 32) {
        __syncthreads();
#pragma unroll
        for (int q = 0; q < 4; q++) {
            int idx = tid + q * 256;
            int r = idx >> 3, c = (idx & 7) * 4;
            float4 w = *reinterpret_cast<const float4*>(W + (size_t)(j0 + r) * K + kc + c);
            Ws[r][c] = w.x; Ws[r][c + 1] = w.y; Ws[r][c + 2] = w.z; Ws[r][c + 3] = w.w;
        }
#pragma unroll
        for (int q = 0; q < 2; q++) {
            int e = tid + q * 256;
            int k = e >> 4, bb = e & 15;
            float xv;
            if (z == 0) xv = emb[(size_t)stok[bb] * E + kc + k];
            else        xv = lh[(size_t)(b0 + bb) * H + kc + k];
            Xs[k][bb] = xv;
        }
        __syncthreads();
#pragma unroll
        for (int k = 0; k < 32; k++) {
            float x0 = Xs[k][tb * 2], x1 = Xs[k][tb * 2 + 1];
#pragma unroll
            for (int q = 0; q < 4; q++) {
                float w = Ws[tj + q * 32][k];
                acc[q][0] += w * x0;
                acc[q][1] += w * x1;
            }
        }
    }
#pragma unroll
    for (int q = 0; q < 4; q++) {
        int j = j0 + tj + q * 32;
        Cdst[(size_t)(b0 + tb * 2) * J3H + j]     = acc[q][0];
        Cdst[(size_t)(b0 + tb * 2 + 1) * J3H + j] = acc[q][1];
    }
}

// ============================================================
// K2: GRU gates; zeros g_ectx.
// ============================================================
__global__ void k_gates(const float* __restrict__ lh,
                        const float* __restrict__ b_ih,
                        const float* __restrict__ b_hh,
                        const float* __restrict__ w_h,
                        const float* __restrict__ w_d,
                        float* __restrict__ out) {
    int b = blockIdx.x >> 2;
    int i = ((blockIdx.x & 3) << 7) + threadIdx.x;
    float gx0 = g_gx[(size_t)b * J3H + i]         + b_ih[i];
    float gh0 = g_gh[(size_t)b * J3H + i]         + b_hh[i];
    float gx1 = g_gx[(size_t)b * J3H + H + i]     + b_ih[H + i];
    float gh1 = g_gh[(size_t)b * J3H + H + i]     + b_hh[H + i];
    float gx2 = g_gx[(size_t)b * J3H + 2 * H + i] + b_ih[2 * H + i];
    float gh2 = g_gh[(size_t)b * J3H + 2 * H + i] + b_hh[2 * H + i];
    float r = 1.f / (1.f + __expf(-(gx0 + gh0)));
    float z = 1.f / (1.f + __expf(-(gx1 + gh1)));
    float n = tanhf(gx2 + r * gh2);
    float hl = lh[(size_t)b * H + i];
    float h = (1.f - z) * n + z * hl;
    g_h[(size_t)b * H + i]   = h;
    g_hw[(size_t)b * H + i]  = h * w_h[i];
    g_hwd[(size_t)b * H + i] = h * w_d[i];
    g_ectx[(size_t)b * H + i] = 0.f;
    out[HH_OFF + (size_t)b * H + i] = h;
    out[DH_OFF + ((size_t)b * (T + 1) + T) * H + i] = h;
}

// ============================================================
// K3: att_scores[b,s] = sum_h hw[b,h]*enc[b,s,h]  (R4-proven)
// ============================================================
__global__ void k_attsc(const float* __restrict__ enc) {
    int wg   = blockIdx.x * 8 + (threadIdx.x >> 5);
    int lane = threadIdx.x & 31;
    int b = wg / S, s = wg % S;
    const float4* e4 = reinterpret_cast<const float4*>(enc + ((size_t)b * S + s) * H);
    const float4* h4 = reinterpret_cast<const float4*>(g_hw + (size_t)b * H);
    float acc = 0.f;
#pragma unroll
    for (int q = 0; q < 4; q++) {
        int idx = q * 32 + lane;
        float4 e = e4[idx], hv = h4[idx];
        acc += e.x * hv.x + e.y * hv.y + e.z * hv.z + e.w * hv.w;
    }
    for (int o = 16; o; o >>= 1) acc += __shfl_xor_sync(0xffffffffu, acc, o);
    if (!lane) g_att_scores[b * S + s] = acc;
}

// ============================================================
// K4: temporal attention + att_dist + new_previous_att (R4-proven)
// ============================================================
__global__ void k_temporal(const float* __restrict__ pa, float* __restrict__ out) {
    __shared__ float red[16];
    int b = blockIdx.x, s = threadIdx.x;
    float tmp = 0.f;
    if (s < S) {
        float denom = 0.f;
        for (int t = 0; t < T; t++) {
            float v = pa[((size_t)b * T + t) * S + s];
            out[NPA_OFF + ((size_t)b * (T + 1) + t) * S + s] = v;
            denom += __expf(v);
        }
        float asc = g_att_scores[b * S + s];
        out[NPA_OFF + ((size_t)b * (T + 1) + T) * S + s] = asc;
        tmp = __expf(asc) / denom;
    }
    float v = tmp;
    for (int o = 16; o; o >>= 1) v += __shfl_xor_sync(0xffffffffu, v, o);
    if ((threadIdx.x & 31) == 0) red[threadIdx.x >> 5] = v;
    __syncthreads();
    if (threadIdx.x < 16) {
        float r = red[threadIdx.x];
        for (int o = 8; o; o >>= 1) r += __shfl_xor_sync(0xffffu, r, o);
        if (!threadIdx.x) red[0] = r;
    }
    __syncthreads();
    if (s < S) out[AD_OFF + (size_t)b * S + s] = tmp / red[0];
}

// ============================================================
// K5: encoder_context partial: grid (5, B), 80 s-rows per block
// ============================================================
__global__ void k_ectx(const float* __restrict__ enc, const float* __restrict__ out_ro) {
    __shared__ float att[80];
    int sy = blockIdx.x, b = blockIdx.y;
    int s0 = sy * 80;
    int h = threadIdx.x;
    if (h < 80) att[h] = out_ro[AD_OFF + (size_t)b * S + s0 + h];
    __syncthreads();
    float a0 = 0, a1 = 0, a2 = 0, a3 = 0, a4 = 0, a5 = 0, a6 = 0, a7 = 0;
    const float* eb = enc + ((size_t)b * S + s0) * H + h;
    for (int s = 0; s < 80; s += 8) {
        a0 += att[s + 0] * eb[(size_t)(s + 0) * H];
        a1 += att[s + 1] * eb[(size_t)(s + 1) * H];
        a2 += att[s + 2] * eb[(size_t)(s + 2) * H];
        a3 += att[s + 3] * eb[(size_t)(s + 3) * H];
        a4 += att[s + 4] * eb[(size_t)(s + 4) * H];
        a5 += att[s + 5] * eb[(size_t)(s + 5) * H];
        a6 += att[s + 6] * eb[(size_t)(s + 6) * H];
        a7 += att[s + 7] * eb[(size_t)(s + 7) * H];
    }
    atomicAdd(&g_ectx[(size_t)b * H + h], ((a0 + a1) + (a2 + a3)) + ((a4 + a5) + (a6 + a7)));
}

// ============================================================
// K6: decoder attention + decoder_context + decoder_h_states copy
// ============================================================
__global__ void k_dec(const float* __restrict__ pds, float* __restrict__ out) {
    extern __shared__ float sm[];
    float* pd = sm;
    float* sc = sm + T * H;
    float* at = sc + 64;
    int b = blockIdx.x, tid = threadIdx.x;
    for (int idx = tid; idx < T * H; idx += 512) {
        float v = pds[(size_t)b * T * H + idx];
        pd[idx] = v;
        int t = idx >> 9, hh = idx & 511;
        out[DH_OFF + ((size_t)b * (T + 1) + t) * H + hh] = v;
    }
    __syncthreads();
    int w = tid >> 5, lane = tid & 31;
    for (int t = w; t < T; t += 16) {
        float acc = 0.f;
#pragma unroll
        for (int q = 0; q < 16; q++)
            acc += g_hwd[(size_t)b * H + q * 32 + lane] * pd[t * H + q * 32 + lane];
        for (int o = 16; o; o >>= 1) acc += __shfl_xor_sync(0xffffffffu, acc, o);
        if (!lane) sc[t] = acc;
    }
    __syncthreads();
    if (tid < 32) {
        float s1 = (tid < T) ? sc[tid] : -1e30f;
        float s2 = (tid + 32 < T) ? sc[tid + 32] : -1e30f;
        float m = fmaxf(s1, s2);
        for (int o = 16; o; o >>= 1) m = fmaxf(m, __shfl_xor_sync(0xffffffffu, m, o));
        float e1 = (tid < T) ? __expf(s1 - m) : 0.f;
        float e2 = (tid + 32 < T) ? __expf(s2 - m) : 0.f;
        float sum = e1 + e2;
        for (int o = 16; o; o >>= 1) sum += __shfl_xor_sync(0xffffffffu, sum, o);
        if (tid < T) at[tid] = e1 / sum;
        if (tid + 32 < T) at[tid + 32] = e2 / sum;
    }
    __syncthreads();
    float acc = 0.f;
    for (int t = 0; t < T; t++) acc += at[t] * pd[t * H + tid];
    g_dctx[(size_t)b * H + tid] = acc;
}

// ============================================================
// K8: logits_h -> bf16 hi/lo split directly (X for vocab GEMM)
// ============================================================
__global__ void k_outh(const float* __restrict__ Wo, const float* __restrict__ bo,
                       const float* __restrict__ ctrl) {
    __shared__ float Ws[8 * 128];
    __shared__ float Cs[32 * 129];
    int el = threadIdx.x >> 5, bl = threadIdx.x & 31;
    int e = blockIdx.x * 8 + el, bb = blockIdx.y * 32 + bl;
    float acc = 0.f;
    for (int kc = 0; kc < 1536; kc += 128) {
        __syncthreads();
        for (int idx = threadIdx.x; idx < 1024; idx += 256) {
            int ee = idx >> 7, k = idx & 127;
            Ws[idx] = Wo[(size_t)(blockIdx.x * 8 + ee) * CB + kc + k];
        }
        const float* src = (kc < 512) ? (g_h + kc)
                         : (kc < 1024) ? (g_ectx + kc - 512)
                                       : (g_dctx + kc - 1024);
        for (int idx = threadIdx.x; idx < 4096; idx += 256) {
            int b2 = idx >> 7, k = idx & 127;
            Cs[b2 * 129 + k] = src[(size_t)(blockIdx.y * 32 + b2) * H + k];
        }
        __syncthreads();
#pragma unroll 8
        for (int k = 0; k < 128; k++)
            acc += Ws[el * 128 + k] * Cs[bl * 129 + k];
    }
    acc += Wo[(size_t)e * CB + 1536] * ctrl[bb];
    float v = acc + bo[e];
    __nv_bfloat16 hi = __float2bfloat16(v);
    __nv_bfloat16 lo = __float2bfloat16(v - __bfloat162float(hi));
    g_xhi[(size_t)bb * E + e] = *reinterpret_cast<unsigned short*>(&hi);
    g_xlo[(size_t)bb * E + e] = *reinterpret_cast<unsigned short*>(&lo);
}

// ============================================================
// K9: p_gen; also zeros g_sumexp (R4-proven)
// ============================================================
__global__ void k_pgen(const float* __restrict__ gw, const float* __restrict__ gb,
                       const float* __restrict__ ctrl, float* __restrict__ out) {
    int b = blockIdx.x * 8 + (threadIdx.x >> 5);
    int lane = threadIdx.x & 31;
    float acc = 0.f;
    for (int k = lane; k < H; k += 32) {
        acc += g_h[(size_t)b * H + k]    * gw[k];
        acc += g_ectx[(size_t)b * H + k] * gw[H + k];
        acc += g_dctx[(size_t)b * H + k] * gw[2 * H + k];
    }
    if (!lane) acc += ctrl[b] * gw[1536];
    for (int o = 16; o; o >>= 1) acc += __shfl_xor_sync(0xffffffffu, acc, o);
    if (!lane) {
        out[PG_OFF + b] = 1.f / (1.f + __expf(-(acc + gb[0])));
        g_sumexp[b] = 0.f;
    }
}

// ============================================================
// K10: vocab GEMM — operands pre-split, NO conversion here.
// Pure smem copy + 3-term HMMA + bias/exp/row-sum epilogue.
// ============================================================
__global__ void __launch_bounds__(512, 1)
k_outv_mma(const float* __restrict__ bv) {
    extern __shared__ char smc[];
    __shared__ float s_bv[128];
    int tid = threadIdx.x;
    int vbase = blockIdx.x * 128;

    if (tid < 128) s_bv[tid] = (vbase + tid < V) ? bv[vbase + tid] : 0.f;

    // copy pre-split bf16 tiles into smem (uint2 = 4 bf16)
#pragma unroll
    for (int q = 0; q < 8; q++) {
        int idx = tid + q * 512;          // 4096 uint2 slots
        int r = idx >> 5;                  // 32 uint2 per 128-col row
        int c = (idx & 31) * 4;
        uint2 wh = make_uint2(0u, 0u), wl = make_uint2(0u, 0u);
        if (vbase + r < V) {
            size_t goff = (size_t)(vbase + r) * E + c;
            wh = *reinterpret_cast<const uint2*>(g_Wvhi + goff);
            wl = *reinterpret_cast<const uint2*>(g_Wvlo + goff);
        }
        size_t soff = (size_t)(r * TSTR + c) * 2;
        *reinterpret_cast<uint2*>(smc + BHI_O + soff) = wh;
        *reinterpret_cast<uint2*>(smc + BLO_O + soff) = wl;
        size_t xoff = (size_t)r * E + c;
        *reinterpret_cast<uint2*>(smc + AHI_O + soff) =
            *reinterpret_cast<const uint2*>(g_xhi + xoff);
        *reinterpret_cast<uint2*>(smc + ALO_O + soff) =
            *reinterpret_cast<const uint2*>(g_xlo + xoff);
    }
    __syncthreads();

    int wid = tid >> 5, lane = tid & 31;
    int wm = wid >> 2, wn = wid & 3;
    int g = lane >> 2, t = lane & 3;

    float acc[2][4][4];
#pragma unroll
    for (int mi = 0; mi < 2; mi++)
#pragma unroll
        for (int ni = 0; ni < 4; ni++)
#pragma unroll
            for (int r = 0; r < 4; r++) acc[mi][ni][r] = 0.f;

    mma_chunk(smc, wm, wn, g, t, acc);
    __syncthreads();

    float* stage = reinterpret_cast<float*>(smc);
#pragma unroll
    for (int mi = 0; mi < 2; mi++) {
        int r0 = wm * 32 + mi * 16 + g;
#pragma unroll
        for (int ni = 0; ni < 4; ni++) {
            int n0 = wn * 32 + ni * 8 + 2 * t;
            bool v0 = (vbase + n0 < V), v1 = (vbase + n0 + 1 < V);
            float e00 = v0 ? __expf(acc[mi][ni][0] + s_bv[n0])     : 0.f;
            float e01 = v1 ? __expf(acc[mi][ni][1] + s_bv[n0 + 1]) : 0.f;
            float e10 = v0 ? __expf(acc[mi][ni][2] + s_bv[n0])     : 0.f;
            float e11 = v1 ? __expf(acc[mi][ni][3] + s_bv[n0 + 1]) : 0.f;
            stage[r0 * TSTR + n0]           = e00;
            stage[r0 * TSTR + n0 + 1]       = e01;
            stage[(r0 + 8) * TSTR + n0]     = e10;
            stage[(r0 + 8) * TSTR + n0 + 1] = e11;
        }
    }
    __syncthreads();

    if (tid < 256) {
        int row = tid >> 1, half = tid & 1;
        float lsum = 0.f;
        for (int c = half * 64; c < half * 64 + 64; c++) lsum += stage[row * TSTR + c];
        atomicAdd(&g_sumexp[row], lsum);
    }
    for (int idx = tid; idx < 128 * 128; idx += 512) {
        int b = idx >> 7, c = idx & 127;
        if (vbase + c < V) g_logits[(size_t)b * V + vbase + c] = stage[b * TSTR + c];
    }
}

// ============================================================
// K11: p_vocab, p_final (vectorized float4)
// ============================================================
__global__ void k_pfinal(float* __restrict__ out) {
    int b = blockIdx.y;
    int v = (blockIdx.x * 256 + threadIdx.x) * 4;
    if (v >= VP) return;
    float pg = out[PG_OFF + b];
    if (v < V) {
        float4 L = *reinterpret_cast<const float4*>(g_logits + (size_t)b * V + v);
        float inv = __fdividef(1.f, g_sumexp[b]);
        float4 p = make_float4(L.x * inv, L.y * inv, L.z * inv, L.w * inv);
        *reinterpret_cast<float4*>(out + PV_OFF + (size_t)b * V + v) = p;
        *reinterpret_cast<float4*>(out + PF_OFF + (size_t)b * VP + v) =
            make_float4(p.x * pg, p.y * pg, p.z * pg, p.w * pg);
    } else {
        *reinterpret_cast<float4*>(out + PF_OFF + (size_t)b * VP + v) =
            make_float4(0.f, 0.f, 0.f, 0.f);
    }
}

// ============================================================
// K12: pointer scatter
// ============================================================
__global__ void k_scatter(const int* __restrict__ fiv, float* __restrict__ out) {
    int b = blockIdx.x, s = threadIdx.x;
    if (s < S) {
        float pg = out[PG_OFF + b];
        float val = (1.f - pg) * out[AD_OFF + (size_t)b * S + s];
        int idx = fiv[(size_t)b * S + s];
        atomicAdd(&out[PF_OFF + (size_t)b * VP + idx], val);
    }
}

// ============================================================
// launch — R4 graph + convW on side stream at t=0
// ============================================================
extern "C" void kernel_launch(void* const* d_in, const int* in_sizes, int n_in,
                              void* d_out, int out_size) {
    const int*   tok    = (const int*)  d_in[0];
    const float* pds    = (const float*)d_in[1];
    const float* lh     = (const float*)d_in[2];
    const float* enc    = (const float*)d_in[3];
    const int*   fiv    = (const int*)  d_in[4];
    const float* pa     = (const float*)d_in[5];
    const float* ctrl   = (const float*)d_in[6];
    const float* emb    = (const float*)d_in[7];
    const float* W_ih   = (const float*)d_in[8];
    const float* W_hh   = (const float*)d_in[9];
    const float* b_ih   = (const float*)d_in[10];
    const float* b_hh   = (const float*)d_in[11];
    const float* w_h    = (const float*)d_in[12];
    const float* w_d    = (const float*)d_in[13];
    const float* gen_W  = (const float*)d_in[14];
    const float* gen_b  = (const float*)d_in[15];
    const float* outh_W = (const float*)d_in[16];
    const float* outh_b = (const float*)d_in[17];
    const float* outv_W = (const float*)d_in[18];
    const float* outv_b = (const float*)d_in[19];
    float* out = (float*)d_out;

    const int DEC_SMEM = (T * H + 128) * sizeof(float);
    cudaFuncSetAttribute(k_dec, cudaFuncAttributeMaxDynamicSharedMemorySize, DEC_SMEM);
    cudaFuncSetAttribute(k_outv_mma, cudaFuncAttributeMaxDynamicSharedMemorySize, MMA_DSMEM);

    cudaStream_t s1;
    cudaStreamCreateWithFlags(&s1, cudaStreamNonBlocking);
    cudaEvent_t evRoot, evGates, evDec, evEctx, evPgen;
    cudaEventCreateWithFlags(&evRoot,  cudaEventDisableTiming);
    cudaEventCreateWithFlags(&evGates, cudaEventDisableTiming);
    cudaEventCreateWithFlags(&evDec,   cudaEventDisableTiming);
    cudaEventCreateWithFlags(&evEctx,  cudaEventDisableTiming);
    cudaEventCreateWithFlags(&evPgen,  cudaEventDisableTiming);

    // fork side stream from origin stream (graph-capture requirement)
    cudaEventRecord(evRoot, 0);
    cudaStreamWaitEvent(s1, evRoot, 0);

    // side stream: W split conversion (depends only on input)
    k_convW<<<(V * E / 4) / 256, 256, 0, s1>>>(outv_W);

    // main stream: GRU
    k_grugemm<<<dim3(J3H / 128, B / 16, 2), 256>>>(W_ih, W_hh, tok, emb, lh);
    k_gates<<<4 * B, 128>>>(lh, b_ih, b_hh, w_h, w_d, out);
    cudaEventRecord(evGates, 0);

    // side stream: decoder attention (needs g_hwd; after convW)
    cudaStreamWaitEvent(s1, evGates, 0);
    k_dec<<<B, 512, DEC_SMEM, s1>>>(pds, out);
    cudaEventRecord(evDec, s1);

    // main stream: encoder attention chain (R4-proven)
    k_attsc<<<(B * S) / 8, 256>>>(enc);
    k_temporal<<<B, 512>>>(pa, out);
    k_ectx<<<dim3(5, B), 512>>>(enc, out);
    cudaEventRecord(evEctx, 0);

    // side stream: p_gen (needs ectx + dctx); zeros g_sumexp
    cudaStreamWaitEvent(s1, evEctx, 0);
    k_pgen<<<16, 256, 0, s1>>>(gen_W, gen_b, ctrl, out);
    cudaEventRecord(evPgen, s1);

    // main stream: output head (writes X-split), vocab GEMM, finals
    cudaStreamWaitEvent(0, evDec, 0);
    k_outh<<<dim3(16, 4), 256>>>(outh_W, outh_b, ctrl);
    cudaStreamWaitEvent(0, evPgen, 0);   // sumexp zeroed before outv atomics
    k_outv_mma<<<(V + 127) / 128, 512, MMA_DSMEM>>>(outv_b);
    k_pfinal<<<dim3((VP / 4 + 255) / 256, B), 256>>>(out);
    k_scatter<<<B, 512>>>(fiv, out);

    cudaEventDestroy(evRoot);
    cudaEventDestroy(evGates);
    cudaEventDestroy(evDec);
    cudaEventDestroy(evEctx);
    cudaEventDestroy(evPgen);
    cudaStreamDestroy(s1);
}

// round 11
// speedup vs baseline: 1.2475x; 1.2475x over previous
#include <cuda_runtime.h>
#include <cuda_bf16.h>
#include <math.h>
#include <stdint.h>

// Problem constants
#define B    128
#define S    400
#define T    50
#define H    512
#define E    128
#define V    50000
#define PADN 1000
#define J3H  1536
#define CB   1537
#define VP   51000

// ---- output layout (flattened tuple, float32) ----
#define PF_OFF  ((size_t)0)
#define PG_OFF  (PF_OFF + (size_t)B*VP)
#define PV_OFF  (PG_OFF + (size_t)B)
#define AD_OFF  (PV_OFF + (size_t)B*V)
#define DH_OFF  (AD_OFF + (size_t)B*S)
#define HH_OFF  (DH_OFF + (size_t)B*(T+1)*H)
#define NPA_OFF (HH_OFF + (size_t)B*H)

// ---- device scratch ----
__device__ __align__(16) float g_gx[B * J3H];
__device__ __align__(16) float g_gh[B * J3H];
__device__ __align__(16) float g_h[B * H];
__device__ __align__(16) float g_hw[B * H];
__device__ __align__(16) float g_hwd[B * H];
__device__ __align__(16) float g_att_scores[B * S];
__device__ __align__(16) float g_ectx[B * H];
__device__ __align__(16) float g_dctx[B * H];
__device__ __align__(16) float g_lhb[B * E];   // logits_h [b][e]
__device__ __align__(16) float g_sumexp[B];

// ---- mma machinery (bf16 3-term split) ----
#define TSTR  132
#define TILEB (128 * TSTR * 2)
#define AHI_O 0
#define ALO_O (TILEB)
#define BHI_O (2 * TILEB)
#define BLO_O (3 * TILEB)
#define MMA_DSMEM (4 * TILEB)

__device__ __forceinline__ void split2(float a, float b, uint32_t& hv, uint32_t& lv) {
    __nv_bfloat162 hi = __float22bfloat162_rn(make_float2(a, b));
    float ra = a - __bfloat162float(hi.x);
    float rb = b - __bfloat162float(hi.y);
    __nv_bfloat162 lo = __float22bfloat162_rn(make_float2(ra, rb));
    hv = *reinterpret_cast<uint32_t*>(&hi);
    lv = *reinterpret_cast<uint32_t*>(&lo);
}
__device__ __forceinline__ void mma16816(float* c, const uint32_t* a, const uint32_t* b) {
    asm volatile(
        "mma.sync.aligned.m16n8k16.row.col.f32.bf16.bf16.f32 "
        "{%0,%1,%2,%3}, {%4,%5,%6,%7}, {%8,%9}, {%0,%1,%2,%3};"
        : "+f"(c[0]), "+f"(c[1]), "+f"(c[2]), "+f"(c[3])
        : "r"(a[0]), "r"(a[1]), "r"(a[2]), "r"(a[3]), "r"(b[0]), "r"(b[1]));
}
__device__ __forceinline__ void mma_chunk(char* smc, int wm, int wn, int g, int t,
                                          float acc[2][4][4]) {
#pragma unroll
    for (int term = 0; term < 3; term++) {
        int aoff = (term == 2) ? ALO_O : AHI_O;
        int boff = (term == 1) ? BLO_O : BHI_O;
#pragma unroll
        for (int ks = 0; ks < 8; ks++) {
            int kb = ks * 16;
            uint32_t af[2][4], bf[4][2];
#pragma unroll
            for (int mi = 0; mi < 2; mi++) {
                int row = wm * 32 + mi * 16 + g;
                size_t o = (size_t)aoff + (size_t)(row * TSTR + kb + 2 * t) * 2;
                af[mi][0] = *reinterpret_cast<const uint32_t*>(smc + o);
                af[mi][1] = *reinterpret_cast<const uint32_t*>(smc + o + 8 * TSTR * 2);
                af[mi][2] = *reinterpret_cast<const uint32_t*>(smc + o + 16);
                af[mi][3] = *reinterpret_cast<const uint32_t*>(smc + o + 8 * TSTR * 2 + 16);
            }
#pragma unroll
            for (int ni = 0; ni < 4; ni++) {
                int row = wn * 32 + ni * 8 + g;
                size_t o = (size_t)boff + (size_t)(row * TSTR + kb + 2 * t) * 2;
                bf[ni][0] = *reinterpret_cast<const uint32_t*>(smc + o);
                bf[ni][1] = *reinterpret_cast<const uint32_t*>(smc + o + 16);
            }
#pragma unroll
            for (int mi = 0; mi < 2; mi++)
#pragma unroll
                for (int ni = 0; ni < 4; ni++)
                    mma16816(acc[mi][ni], af[mi], bf[ni]);
        }
    }
}

// ============================================================
// K1: fused GRU GEMMs, smem-tiled (R4 champion)
// ============================================================
__global__ void __launch_bounds__(256) k_grugemm(const float* __restrict__ Wih,
                                                 const float* __restrict__ Whh,
                                                 const int* __restrict__ tok,
                                                 const float* __restrict__ emb,
                                                 const float* __restrict__ lh) {
    int z = blockIdx.z;
    const float* W = z ? Whh : Wih;
    float* Cdst    = z ? g_gh : g_gx;
    int K = z ? H : E;

    __shared__ float Ws[128][33];
    __shared__ float Xs[32][17];
    __shared__ int stok[16];
    int tid = threadIdx.x;
    int j0 = blockIdx.x * 128, b0 = blockIdx.y * 16;
    if (tid < 16) stok[tid] = tok[b0 + tid];
    int tj = tid & 31, tb = tid >> 5;
    float acc[4][2];
#pragma unroll
    for (int q = 0; q < 4; q++) { acc[q][0] = 0.f; acc[q][1] = 0.f; }

    for (int kc = 0; kc < K; kc += 32) {
        __syncthreads();
#pragma unroll
        for (int q = 0; q < 4; q++) {
            int idx = tid + q * 256;
            int r = idx >> 3, c = (idx & 7) * 4;
            float4 w = *reinterpret_cast<const float4*>(W + (size_t)(j0 + r) * K + kc + c);
            Ws[r][c] = w.x; Ws[r][c + 1] = w.y; Ws[r][c + 2] = w.z; Ws[r][c + 3] = w.w;
        }
#pragma unroll
        for (int q = 0; q < 2; q++) {
            int e = tid + q * 256;
            int k = e >> 4, bb = e & 15;
            float xv;
            if (z == 0) xv = emb[(size_t)stok[bb] * E + kc + k];
            else        xv = lh[(size_t)(b0 + bb) * H + kc + k];
            Xs[k][bb] = xv;
        }
        __syncthreads();
#pragma unroll
        for (int k = 0; k < 32; k++) {
            float x0 = Xs[k][tb * 2], x1 = Xs[k][tb * 2 + 1];
#pragma unroll
            for (int q = 0; q < 4; q++) {
                float w = Ws[tj + q * 32][k];
                acc[q][0] += w * x0;
                acc[q][1] += w * x1;
            }
        }
    }
#pragma unroll
    for (int q = 0; q < 4; q++) {
        int j = j0 + tj + q * 32;
        Cdst[(size_t)(b0 + tb * 2) * J3H + j]     = acc[q][0];
        Cdst[(size_t)(b0 + tb * 2 + 1) * J3H + j] = acc[q][1];
    }
}

// ============================================================
// K2: GRU gates; zeros g_ectx (R4 champion)
// ============================================================
__global__ void k_gates(const float* __restrict__ lh,
                        const float* __restrict__ b_ih,
                        const float* __restrict__ b_hh,
                        const float* __restrict__ w_h,
                        const float* __restrict__ w_d,
                        float* __restrict__ out) {
    int b = blockIdx.x >> 2;
    int i = ((blockIdx.x & 3) << 7) + threadIdx.x;
    float gx0 = g_gx[(size_t)b * J3H + i]         + b_ih[i];
    float gh0 = g_gh[(size_t)b * J3H + i]         + b_hh[i];
    float gx1 = g_gx[(size_t)b * J3H + H + i]     + b_ih[H + i];
    float gh1 = g_gh[(size_t)b * J3H + H + i]     + b_hh[H + i];
    float gx2 = g_gx[(size_t)b * J3H + 2 * H + i] + b_ih[2 * H + i];
    float gh2 = g_gh[(size_t)b * J3H + 2 * H + i] + b_hh[2 * H + i];
    float r = 1.f / (1.f + __expf(-(gx0 + gh0)));
    float z = 1.f / (1.f + __expf(-(gx1 + gh1)));
    float n = tanhf(gx2 + r * gh2);
    float hl = lh[(size_t)b * H + i];
    float h = (1.f - z) * n + z * hl;
    g_h[(size_t)b * H + i]   = h;
    g_hw[(size_t)b * H + i]  = h * w_h[i];
    g_hwd[(size_t)b * H + i] = h * w_d[i];
    g_ectx[(size_t)b * H + i] = 0.f;
    out[HH_OFF + (size_t)b * H + i] = h;
    out[DH_OFF + ((size_t)b * (T + 1) + T) * H + i] = h;
}

// ============================================================
// K3: att_scores (R4 champion)
// ============================================================
__global__ void k_attsc(const float* __restrict__ enc) {
    int wg   = blockIdx.x * 8 + (threadIdx.x >> 5);
    int lane = threadIdx.x & 31;
    int b = wg / S, s = wg % S;
    const float4* e4 = reinterpret_cast<const float4*>(enc + ((size_t)b * S + s) * H);
    const float4* h4 = reinterpret_cast<const float4*>(g_hw + (size_t)b * H);
    float acc = 0.f;
#pragma unroll
    for (int q = 0; q < 4; q++) {
        int idx = q * 32 + lane;
        float4 e = e4[idx], hv = h4[idx];
        acc += e.x * hv.x + e.y * hv.y + e.z * hv.z + e.w * hv.w;
    }
    for (int o = 16; o; o >>= 1) acc += __shfl_xor_sync(0xffffffffu, acc, o);
    if (!lane) g_att_scores[b * S + s] = acc;
}

// ============================================================
// K4: temporal attention (R4 champion)
// ============================================================
__global__ void k_temporal(const float* __restrict__ pa, float* __restrict__ out) {
    __shared__ float red[16];
    int b = blockIdx.x, s = threadIdx.x;
    float tmp = 0.f;
    if (s < S) {
        float denom = 0.f;
        for (int t = 0; t < T; t++) {
            float v = pa[((size_t)b * T + t) * S + s];
            out[NPA_OFF + ((size_t)b * (T + 1) + t) * S + s] = v;
            denom += __expf(v);
        }
        float asc = g_att_scores[b * S + s];
        out[NPA_OFF + ((size_t)b * (T + 1) + T) * S + s] = asc;
        tmp = __expf(asc) / denom;
    }
    float v = tmp;
    for (int o = 16; o; o >>= 1) v += __shfl_xor_sync(0xffffffffu, v, o);
    if ((threadIdx.x & 31) == 0) red[threadIdx.x >> 5] = v;
    __syncthreads();
    if (threadIdx.x < 16) {
        float r = red[threadIdx.x];
        for (int o = 8; o; o >>= 1) r += __shfl_xor_sync(0xffffu, r, o);
        if (!threadIdx.x) red[0] = r;
    }
    __syncthreads();
    if (s < S) out[AD_OFF + (size_t)b * S + s] = tmp / red[0];
}

// ============================================================
// K5: encoder_context partial (R4 champion)
// ============================================================
__global__ void k_ectx(const float* __restrict__ enc, const float* __restrict__ out_ro) {
    __shared__ float att[80];
    int sy = blockIdx.x, b = blockIdx.y;
    int s0 = sy * 80;
    int h = threadIdx.x;
    if (h < 80) att[h] = out_ro[AD_OFF + (size_t)b * S + s0 + h];
    __syncthreads();
    float a0 = 0, a1 = 0, a2 = 0, a3 = 0, a4 = 0, a5 = 0, a6 = 0, a7 = 0;
    const float* eb = enc + ((size_t)b * S + s0) * H + h;
    for (int s = 0; s < 80; s += 8) {
        a0 += att[s + 0] * eb[(size_t)(s + 0) * H];
        a1 += att[s + 1] * eb[(size_t)(s + 1) * H];
        a2 += att[s + 2] * eb[(size_t)(s + 2) * H];
        a3 += att[s + 3] * eb[(size_t)(s + 3) * H];
        a4 += att[s + 4] * eb[(size_t)(s + 4) * H];
        a5 += att[s + 5] * eb[(size_t)(s + 5) * H];
        a6 += att[s + 6] * eb[(size_t)(s + 6) * H];
        a7 += att[s + 7] * eb[(size_t)(s + 7) * H];
    }
    atomicAdd(&g_ectx[(size_t)b * H + h], ((a0 + a1) + (a2 + a3)) + ((a4 + a5) + (a6 + a7)));
}

// ============================================================
// K6: decoder attention + DH copy (R4 champion)
// ============================================================
__global__ void k_dec(const float* __restrict__ pds, float* __restrict__ out) {
    extern __shared__ float sm[];
    float* pd = sm;
    float* sc = sm + T * H;
    float* at = sc + 64;
    int b = blockIdx.x, tid = threadIdx.x;
    for (int idx = tid; idx < T * H; idx += 512) {
        float v = pds[(size_t)b * T * H + idx];
        pd[idx] = v;
        int t = idx >> 9, hh = idx & 511;
        out[DH_OFF + ((size_t)b * (T + 1) + t) * H + hh] = v;
    }
    __syncthreads();
    int w = tid >> 5, lane = tid & 31;
    for (int t = w; t < T; t += 16) {
        float acc = 0.f;
#pragma unroll
        for (int q = 0; q < 16; q++)
            acc += g_hwd[(size_t)b * H + q * 32 + lane] * pd[t * H + q * 32 + lane];
        for (int o = 16; o; o >>= 1) acc += __shfl_xor_sync(0xffffffffu, acc, o);
        if (!lane) sc[t] = acc;
    }
    __syncthreads();
    if (tid < 32) {
        float s1 = (tid < T) ? sc[tid] : -1e30f;
        float s2 = (tid + 32 < T) ? sc[tid + 32] : -1e30f;
        float m = fmaxf(s1, s2);
        for (int o = 16; o; o >>= 1) m = fmaxf(m, __shfl_xor_sync(0xffffffffu, m, o));
        float e1 = (tid < T) ? __expf(s1 - m) : 0.f;
        float e2 = (tid + 32 < T) ? __expf(s2 - m) : 0.f;
        float sum = e1 + e2;
        for (int o = 16; o; o >>= 1) sum += __shfl_xor_sync(0xffffffffu, sum, o);
        if (tid < T) at[tid] = e1 / sum;
        if (tid + 32 < T) at[tid + 32] = e2 / sum;
    }
    __syncthreads();
    float acc = 0.f;
    for (int t = 0; t < T; t++) acc += at[t] * pd[t * H + tid];
    g_dctx[(size_t)b * H + tid] = acc;
}

// ============================================================
// K8: logits_h (R4 champion, gathers combined on the fly)
// ============================================================
__global__ void k_outh(const float* __restrict__ Wo, const float* __restrict__ bo,
                       const float* __restrict__ ctrl) {
    __shared__ float Ws[8 * 128];
    __shared__ float Cs[32 * 129];
    int el = threadIdx.x >> 5, bl = threadIdx.x & 31;
    int e = blockIdx.x * 8 + el, bb = blockIdx.y * 32 + bl;
    float acc = 0.f;
    for (int kc = 0; kc < 1536; kc += 128) {
        __syncthreads();
        for (int idx = threadIdx.x; idx < 1024; idx += 256) {
            int ee = idx >> 7, k = idx & 127;
            Ws[idx] = Wo[(size_t)(blockIdx.x * 8 + ee) * CB + kc + k];
        }
        const float* src = (kc < 512) ? (g_h + kc)
                         : (kc < 1024) ? (g_ectx + kc - 512)
                                       : (g_dctx + kc - 1024);
        for (int idx = threadIdx.x; idx < 4096; idx += 256) {
            int b2 = idx >> 7, k = idx & 127;
            Cs[b2 * 129 + k] = src[(size_t)(blockIdx.y * 32 + b2) * H + k];
        }
        __syncthreads();
#pragma unroll 8
        for (int k = 0; k < 128; k++)
            acc += Ws[el * 128 + k] * Cs[bl * 129 + k];
    }
    acc += Wo[(size_t)e * CB + 1536] * ctrl[bb];
    g_lhb[(size_t)bb * E + e] = acc + bo[e];
}

// ============================================================
// K9: p_gen; zeros g_sumexp (R4 champion)
// ============================================================
__global__ void k_pgen(const float* __restrict__ gw, const float* __restrict__ gb,
                       const float* __restrict__ ctrl, float* __restrict__ out) {
    int b = blockIdx.x * 8 + (threadIdx.x >> 5);
    int lane = threadIdx.x & 31;
    float acc = 0.f;
    for (int k = lane; k < H; k += 32) {
        acc += g_h[(size_t)b * H + k]    * gw[k];
        acc += g_ectx[(size_t)b * H + k] * gw[H + k];
        acc += g_dctx[(size_t)b * H + k] * gw[2 * H + k];
    }
    if (!lane) acc += ctrl[b] * gw[1536];
    for (int o = 16; o; o >>= 1) acc += __shfl_xor_sync(0xffffffffu, acc, o);
    if (!lane) {
        out[PG_OFF + b] = 1.f / (1.f + __expf(-(acc + gb[0])));
        g_sumexp[b] = 0.f;
    }
}

// ============================================================
// K10: vocab GEMM (mma split, inline conversion — R4 champion)
// ONLY change: exp(logits) written DIRECTLY into p_vocab slot.
// ============================================================
__global__ void __launch_bounds__(512, 1)
k_outv_mma(const float* __restrict__ Wv, const float* __restrict__ bv,
           float* __restrict__ out) {
    extern __shared__ char smc[];
    __shared__ float s_bv[128];
    int tid = threadIdx.x;
    int vbase = blockIdx.x * 128;

    if (tid < 128) s_bv[tid] = (vbase + tid < V) ? bv[vbase + tid] : 0.f;

#pragma unroll
    for (int q = 0; q < 8; q++) {
        int idx = tid + q * 512;
        int r = idx >> 5;
        int c = (idx & 31) * 4;
        float4 w = make_float4(0.f, 0.f, 0.f, 0.f);
        if (vbase + r < V) w = *reinterpret_cast<const float4*>(Wv + (size_t)(vbase + r) * E + c);
        uint32_t h0, l0, h1, l1;
        split2(w.x, w.y, h0, l0);
        split2(w.z, w.w, h1, l1);
        size_t off = (size_t)(r * TSTR + c) * 2;
        *reinterpret_cast<uint2*>(smc + BHI_O + off) = make_uint2(h0, h1);
        *reinterpret_cast<uint2*>(smc + BLO_O + off) = make_uint2(l0, l1);
        float4 x = *reinterpret_cast<const float4*>(g_lhb + (size_t)r * E + c);
        split2(x.x, x.y, h0, l0);
        split2(x.z, x.w, h1, l1);
        *reinterpret_cast<uint2*>(smc + AHI_O + off) = make_uint2(h0, h1);
        *reinterpret_cast<uint2*>(smc + ALO_O + off) = make_uint2(l0, l1);
    }
    __syncthreads();

    int wid = tid >> 5, lane = tid & 31;
    int wm = wid >> 2, wn = wid & 3;
    int g = lane >> 2, t = lane & 3;

    float acc[2][4][4];
#pragma unroll
    for (int mi = 0; mi < 2; mi++)
#pragma unroll
        for (int ni = 0; ni < 4; ni++)
#pragma unroll
            for (int r = 0; r < 4; r++) acc[mi][ni][r] = 0.f;

    mma_chunk(smc, wm, wn, g, t, acc);
    __syncthreads();

    float* stage = reinterpret_cast<float*>(smc);
#pragma unroll
    for (int mi = 0; mi < 2; mi++) {
        int r0 = wm * 32 + mi * 16 + g;
#pragma unroll
        for (int ni = 0; ni < 4; ni++) {
            int n0 = wn * 32 + ni * 8 + 2 * t;
            bool v0 = (vbase + n0 < V), v1 = (vbase + n0 + 1 < V);
            float e00 = v0 ? __expf(acc[mi][ni][0] + s_bv[n0])     : 0.f;
            float e01 = v1 ? __expf(acc[mi][ni][1] + s_bv[n0 + 1]) : 0.f;
            float e10 = v0 ? __expf(acc[mi][ni][2] + s_bv[n0])     : 0.f;
            float e11 = v1 ? __expf(acc[mi][ni][3] + s_bv[n0 + 1]) : 0.f;
            stage[r0 * TSTR + n0]           = e00;
            stage[r0 * TSTR + n0 + 1]       = e01;
            stage[(r0 + 8) * TSTR + n0]     = e10;
            stage[(r0 + 8) * TSTR + n0 + 1] = e11;
        }
    }
    __syncthreads();

    if (tid < 256) {
        int row = tid >> 1, half = tid & 1;
        float lsum = 0.f;
        for (int c = half * 64; c < half * 64 + 64; c++) lsum += stage[row * TSTR + c];
        atomicAdd(&g_sumexp[row], lsum);
    }
    for (int idx = tid; idx < 128 * 128; idx += 512) {
        int b = idx >> 7, c = idx & 127;
        if (vbase + c < V)
            out[PV_OFF + (size_t)b * V + vbase + c] = stage[b * TSTR + c];
    }
}

// ============================================================
// K11: normalize p_vocab in place + p_final (float4)
// ============================================================
__global__ void k_pfinal(float* __restrict__ out) {
    int b = blockIdx.y;
    int v = (blockIdx.x * 256 + threadIdx.x) * 4;
    if (v >= VP) return;
    float pg = out[PG_OFF + b];
    if (v < V) {
        float4 u = *reinterpret_cast<const float4*>(out + PV_OFF + (size_t)b * V + v);
        float inv = __fdividef(1.f, g_sumexp[b]);
        float4 p = make_float4(u.x * inv, u.y * inv, u.z * inv, u.w * inv);
        *reinterpret_cast<float4*>(out + PV_OFF + (size_t)b * V + v) = p;
        *reinterpret_cast<float4*>(out + PF_OFF + (size_t)b * VP + v) =
            make_float4(p.x * pg, p.y * pg, p.z * pg, p.w * pg);
    } else {
        *reinterpret_cast<float4*>(out + PF_OFF + (size_t)b * VP + v) =
            make_float4(0.f, 0.f, 0.f, 0.f);
    }
}

// ============================================================
// K12: pointer scatter
// ============================================================
__global__ void k_scatter(const int* __restrict__ fiv, float* __restrict__ out) {
    int b = blockIdx.x, s = threadIdx.x;
    if (s < S) {
        float pg = out[PG_OFF + b];
        float val = (1.f - pg) * out[AD_OFF + (size_t)b * S + s];
        int idx = fiv[(size_t)b * S + s];
        atomicAdd(&out[PF_OFF + (size_t)b * VP + idx], val);
    }
}

// ============================================================
// launch — R4 champion graph, unchanged
// ============================================================
extern "C" void kernel_launch(void* const* d_in, const int* in_sizes, int n_in,
                              void* d_out, int out_size) {
    const int*   tok    = (const int*)  d_in[0];
    const float* pds    = (const float*)d_in[1];
    const float* lh     = (const float*)d_in[2];
    const float* enc    = (const float*)d_in[3];
    const int*   fiv    = (const int*)  d_in[4];
    const float* pa     = (const float*)d_in[5];
    const float* ctrl   = (const float*)d_in[6];
    const float* emb    = (const float*)d_in[7];
    const float* W_ih   = (const float*)d_in[8];
    const float* W_hh   = (const float*)d_in[9];
    const float* b_ih   = (const float*)d_in[10];
    const float* b_hh   = (const float*)d_in[11];
    const float* w_h    = (const float*)d_in[12];
    const float* w_d    = (const float*)d_in[13];
    const float* gen_W  = (const float*)d_in[14];
    const float* gen_b  = (const float*)d_in[15];
    const float* outh_W = (const float*)d_in[16];
    const float* outh_b = (const float*)d_in[17];
    const float* outv_W = (const float*)d_in[18];
    const float* outv_b = (const float*)d_in[19];
    float* out = (float*)d_out;

    const int DEC_SMEM = (T * H + 128) * sizeof(float);
    cudaFuncSetAttribute(k_dec, cudaFuncAttributeMaxDynamicSharedMemorySize, DEC_SMEM);
    cudaFuncSetAttribute(k_outv_mma, cudaFuncAttributeMaxDynamicSharedMemorySize, MMA_DSMEM);

    cudaStream_t s1;
    cudaStreamCreateWithFlags(&s1, cudaStreamNonBlocking);
    cudaEvent_t evGates, evDec, evEctx, evPgen;
    cudaEventCreateWithFlags(&evGates, cudaEventDisableTiming);
    cudaEventCreateWithFlags(&evDec,   cudaEventDisableTiming);
    cudaEventCreateWithFlags(&evEctx,  cudaEventDisableTiming);
    cudaEventCreateWithFlags(&evPgen,  cudaEventDisableTiming);

    // main stream: GRU
    k_grugemm<<<dim3(J3H / 128, B / 16, 2), 256>>>(W_ih, W_hh, tok, emb, lh);
    k_gates<<<4 * B, 128>>>(lh, b_ih, b_hh, w_h, w_d, out);
    cudaEventRecord(evGates, 0);

    // side stream: decoder attention (fork via event wait — capture-legal)
    cudaStreamWaitEvent(s1, evGates, 0);
    k_dec<<<B, 512, DEC_SMEM, s1>>>(pds, out);
    cudaEventRecord(evDec, s1);

    // main stream: encoder attention chain
    k_attsc<<<(B * S) / 8, 256>>>(enc);
    k_temporal<<<B, 512>>>(pa, out);
    k_ectx<<<dim3(5, B), 512>>>(enc, out);
    cudaEventRecord(evEctx, 0);

    // side stream: p_gen (needs ectx + dctx); zeros g_sumexp
    cudaStreamWaitEvent(s1, evEctx, 0);
    k_pgen<<<16, 256, 0, s1>>>(gen_W, gen_b, ctrl, out);
    cudaEventRecord(evPgen, s1);

    // main stream: output head, vocab GEMM, finals
    cudaStreamWaitEvent(0, evDec, 0);
    k_outh<<<dim3(16, 4), 256>>>(outh_W, outh_b, ctrl);
    cudaStreamWaitEvent(0, evPgen, 0);   // sumexp zeroed before outv atomics
    k_outv_mma<<<(V + 127) / 128, 512, MMA_DSMEM>>>(outv_W, outv_b, out);
    k_pfinal<<<dim3((VP / 4 + 255) / 256, B), 256>>>(out);
    k_scatter<<<B, 512>>>(fiv, out);

    cudaEventDestroy(evGates);
    cudaEventDestroy(evDec);
    cudaEventDestroy(evEctx);
    cudaEventDestroy(evPgen);
    cudaStreamDestroy(s1);
}

// round 12
// speedup vs baseline: 1.2554x; 1.0063x over previous
#include <cuda_runtime.h>
#include <cuda_bf16.h>
#include <math.h>
#include <stdint.h>

// Problem constants
#define B    128
#define S    400
#define T    50
#define H    512
#define E    128
#define V    50000
#define PADN 1000
#define J3H  1536
#define CB   1537
#define VP   51000

// ---- output layout (flattened tuple, float32) ----
#define PF_OFF  ((size_t)0)
#define PG_OFF  (PF_OFF + (size_t)B*VP)
#define PV_OFF  (PG_OFF + (size_t)B)
#define AD_OFF  (PV_OFF + (size_t)B*V)
#define DH_OFF  (AD_OFF + (size_t)B*S)
#define HH_OFF  (DH_OFF + (size_t)B*(T+1)*H)
#define NPA_OFF (HH_OFF + (size_t)B*H)

// ---- device scratch ----
__device__ __align__(16) float g_gx[B * J3H];
__device__ __align__(16) float g_gh[B * J3H];
__device__ __align__(16) float g_h[B * H];
__device__ __align__(16) float g_hw[B * H];
__device__ __align__(16) float g_hwd[B * H];
__device__ __align__(16) float g_att_scores[B * S];
__device__ __align__(16) float g_tu[B * S];     // unnormalized temporal
__device__ __align__(16) float g_sumT[B];
__device__ __align__(16) float g_ectx[B * H];
__device__ __align__(16) float g_dctx[B * H];
__device__ __align__(16) float g_lhb[B * E];    // logits_h [b][e]
__device__ __align__(16) float g_sumexp[B];

// ---- mma machinery (bf16 3-term split) ----
#define TSTR  132
#define TILEB (128 * TSTR * 2)
#define AHI_O 0
#define ALO_O (TILEB)
#define BHI_O (2 * TILEB)
#define BLO_O (3 * TILEB)
#define MMA_DSMEM (4 * TILEB)

__device__ __forceinline__ void split2(float a, float b, uint32_t& hv, uint32_t& lv) {
    __nv_bfloat162 hi = __float22bfloat162_rn(make_float2(a, b));
    float ra = a - __bfloat162float(hi.x);
    float rb = b - __bfloat162float(hi.y);
    __nv_bfloat162 lo = __float22bfloat162_rn(make_float2(ra, rb));
    hv = *reinterpret_cast<uint32_t*>(&hi);
    lv = *reinterpret_cast<uint32_t*>(&lo);
}
__device__ __forceinline__ void mma16816(float* c, const uint32_t* a, const uint32_t* b) {
    asm volatile(
        "mma.sync.aligned.m16n8k16.row.col.f32.bf16.bf16.f32 "
        "{%0,%1,%2,%3}, {%4,%5,%6,%7}, {%8,%9}, {%0,%1,%2,%3};"
        : "+f"(c[0]), "+f"(c[1]), "+f"(c[2]), "+f"(c[3])
        : "r"(a[0]), "r"(a[1]), "r"(a[2]), "r"(a[3]), "r"(b[0]), "r"(b[1]));
}
__device__ __forceinline__ void mma_chunk(char* smc, int wm, int wn, int g, int t,
                                          float acc[2][4][4]) {
#pragma unroll
    for (int term = 0; term < 3; term++) {
        int aoff = (term == 2) ? ALO_O : AHI_O;
        int boff = (term == 1) ? BLO_O : BHI_O;
#pragma unroll
        for (int ks = 0; ks < 8; ks++) {
            int kb = ks * 16;
            uint32_t af[2][4], bf[4][2];
#pragma unroll
            for (int mi = 0; mi < 2; mi++) {
                int row = wm * 32 + mi * 16 + g;
                size_t o = (size_t)aoff + (size_t)(row * TSTR + kb + 2 * t) * 2;
                af[mi][0] = *reinterpret_cast<const uint32_t*>(smc + o);
                af[mi][1] = *reinterpret_cast<const uint32_t*>(smc + o + 8 * TSTR * 2);
                af[mi][2] = *reinterpret_cast<const uint32_t*>(smc + o + 16);
                af[mi][3] = *reinterpret_cast<const uint32_t*>(smc + o + 8 * TSTR * 2 + 16);
            }
#pragma unroll
            for (int ni = 0; ni < 4; ni++) {
                int row = wn * 32 + ni * 8 + g;
                size_t o = (size_t)boff + (size_t)(row * TSTR + kb + 2 * t) * 2;
                bf[ni][0] = *reinterpret_cast<const uint32_t*>(smc + o);
                bf[ni][1] = *reinterpret_cast<const uint32_t*>(smc + o + 16);
            }
#pragma unroll
            for (int mi = 0; mi < 2; mi++)
#pragma unroll
                for (int ni = 0; ni < 4; ni++)
                    mma16816(acc[mi][ni], af[mi], bf[ni]);
        }
    }
}

// ============================================================
// K1: fused GRU GEMMs, smem-tiled (champion)
// ============================================================
__global__ void __launch_bounds__(256) k_grugemm(const float* __restrict__ Wih,
                                                 const float* __restrict__ Whh,
                                                 const int* __restrict__ tok,
                                                 const float* __restrict__ emb,
                                                 const float* __restrict__ lh) {
    int z = blockIdx.z;
    const float* W = z ? Whh : Wih;
    float* Cdst    = z ? g_gh : g_gx;
    int K = z ? H : E;

    __shared__ float Ws[128][33];
    __shared__ float Xs[32][17];
    __shared__ int stok[16];
    int tid = threadIdx.x;
    int j0 = blockIdx.x * 128, b0 = blockIdx.y * 16;
    if (tid < 16) stok[tid] = tok[b0 + tid];
    int tj = tid & 31, tb = tid >> 5;
    float acc[4][2];
#pragma unroll
    for (int q = 0; q < 4; q++) { acc[q][0] = 0.f; acc[q][1] = 0.f; }

    for (int kc = 0; kc < K; kc += 32) {
        __syncthreads();
#pragma unroll
        for (int q = 0; q < 4; q++) {
            int idx = tid + q * 256;
            int r = idx >> 3, c = (idx & 7) * 4;
            float4 w = *reinterpret_cast<const float4*>(W + (size_t)(j0 + r) * K + kc + c);
            Ws[r][c] = w.x; Ws[r][c + 1] = w.y; Ws[r][c + 2] = w.z; Ws[r][c + 3] = w.w;
        }
#pragma unroll
        for (int q = 0; q < 2; q++) {
            int e = tid + q * 256;
            int k = e >> 4, bb = e & 15;
            float xv;
            if (z == 0) xv = emb[(size_t)stok[bb] * E + kc + k];
            else        xv = lh[(size_t)(b0 + bb) * H + kc + k];
            Xs[k][bb] = xv;
        }
        __syncthreads();
#pragma unroll
        for (int k = 0; k < 32; k++) {
            float x0 = Xs[k][tb * 2], x1 = Xs[k][tb * 2 + 1];
#pragma unroll
            for (int q = 0; q < 4; q++) {
                float w = Ws[tj + q * 32][k];
                acc[q][0] += w * x0;
                acc[q][1] += w * x1;
            }
        }
    }
#pragma unroll
    for (int q = 0; q < 4; q++) {
        int j = j0 + tj + q * 32;
        Cdst[(size_t)(b0 + tb * 2) * J3H + j]     = acc[q][0];
        Cdst[(size_t)(b0 + tb * 2 + 1) * J3H + j] = acc[q][1];
    }
}

// ============================================================
// K2: GRU gates; zeros g_ectx and g_sumT (champion + sumT zero)
// ============================================================
__global__ void k_gates(const float* __restrict__ lh,
                        const float* __restrict__ b_ih,
                        const float* __restrict__ b_hh,
                        const float* __restrict__ w_h,
                        const float* __restrict__ w_d,
                        float* __restrict__ out) {
    int b = blockIdx.x >> 2;
    int i = ((blockIdx.x & 3) << 7) + threadIdx.x;
    if ((blockIdx.x & 3) == 0 && threadIdx.x == 0) g_sumT[b] = 0.f;
    float gx0 = g_gx[(size_t)b * J3H + i]         + b_ih[i];
    float gh0 = g_gh[(size_t)b * J3H + i]         + b_hh[i];
    float gx1 = g_gx[(size_t)b * J3H + H + i]     + b_ih[H + i];
    float gh1 = g_gh[(size_t)b * J3H + H + i]     + b_hh[H + i];
    float gx2 = g_gx[(size_t)b * J3H + 2 * H + i] + b_ih[2 * H + i];
    float gh2 = g_gh[(size_t)b * J3H + 2 * H + i] + b_hh[2 * H + i];
    float r = 1.f / (1.f + __expf(-(gx0 + gh0)));
    float z = 1.f / (1.f + __expf(-(gx1 + gh1)));
    float n = tanhf(gx2 + r * gh2);
    float hl = lh[(size_t)b * H + i];
    float h = (1.f - z) * n + z * hl;
    g_h[(size_t)b * H + i]   = h;
    g_hw[(size_t)b * H + i]  = h * w_h[i];
    g_hwd[(size_t)b * H + i] = h * w_d[i];
    g_ectx[(size_t)b * H + i] = 0.f;
    out[HH_OFF + (size_t)b * H + i] = h;
    out[DH_OFF + ((size_t)b * (T + 1) + T) * H + i] = h;
}

// ============================================================
// K3: att_scores (champion, untouched)
// ============================================================
__global__ void k_attsc(const float* __restrict__ enc) {
    int wg   = blockIdx.x * 8 + (threadIdx.x >> 5);
    int lane = threadIdx.x & 31;
    int b = wg / S, s = wg % S;
    const float4* e4 = reinterpret_cast<const float4*>(enc + ((size_t)b * S + s) * H);
    const float4* h4 = reinterpret_cast<const float4*>(g_hw + (size_t)b * H);
    float acc = 0.f;
#pragma unroll
    for (int q = 0; q < 4; q++) {
        int idx = q * 32 + lane;
        float4 e = e4[idx], hv = h4[idx];
        acc += e.x * hv.x + e.y * hv.y + e.z * hv.z + e.w * hv.w;
    }
    for (int o = 16; o; o >>= 1) acc += __shfl_xor_sync(0xffffffffu, acc, o);
    if (!lane) g_att_scores[b * S + s] = acc;
}

// ============================================================
// K4: temporal (parallelized): grid (2,B) x 256; tu + atomic sumT;
// npa copy + npa[T] write. att_dist write moved to k_ectx.
// ============================================================
__global__ void k_temporal(const float* __restrict__ pa, float* __restrict__ out) {
    int b = blockIdx.y;
    int s = blockIdx.x * 200 + threadIdx.x;   // 256 threads, s < (bx+1)*200
    float tmp = 0.f;
    bool valid = (threadIdx.x < 200);
    if (valid) {
        float denom = 0.f;
        for (int t = 0; t < T; t++) {
            float v = pa[((size_t)b * T + t) * S + s];
            out[NPA_OFF + ((size_t)b * (T + 1) + t) * S + s] = v;
            denom += __expf(v);
        }
        float asc = g_att_scores[b * S + s];
        out[NPA_OFF + ((size_t)b * (T + 1) + T) * S + s] = asc;
        tmp = __expf(asc) / denom;
        g_tu[(size_t)b * S + s] = tmp;
    }
    float v = tmp;
    for (int o = 16; o; o >>= 1) v += __shfl_xor_sync(0xffffffffu, v, o);
    if ((threadIdx.x & 31) == 0 && v != 0.f) atomicAdd(&g_sumT[b], v);
}

// ============================================================
// K5: encoder_context + att_dist: grid (10, B), 40 s-rows per block
// ============================================================
__global__ void k_ectx(const float* __restrict__ enc, float* __restrict__ out) {
    __shared__ float att[40];
    int sy = blockIdx.x, b = blockIdx.y;
    int s0 = sy * 40;
    int h = threadIdx.x;   // 512
    float rsum = __fdividef(1.f, g_sumT[b]);
    if (h < 40) {
        float a = g_tu[(size_t)b * S + s0 + h] * rsum;
        att[h] = a;
        out[AD_OFF + (size_t)b * S + s0 + h] = a;
    }
    __syncthreads();
    float a0 = 0, a1 = 0, a2 = 0, a3 = 0, a4 = 0, a5 = 0, a6 = 0, a7 = 0;
    const float* eb = enc + ((size_t)b * S + s0) * H + h;
#pragma unroll
    for (int s = 0; s < 40; s += 8) {
        a0 += att[s + 0] * eb[(size_t)(s + 0) * H];
        a1 += att[s + 1] * eb[(size_t)(s + 1) * H];
        a2 += att[s + 2] * eb[(size_t)(s + 2) * H];
        a3 += att[s + 3] * eb[(size_t)(s + 3) * H];
        a4 += att[s + 4] * eb[(size_t)(s + 4) * H];
        a5 += att[s + 5] * eb[(size_t)(s + 5) * H];
        a6 += att[s + 6] * eb[(size_t)(s + 6) * H];
        a7 += att[s + 7] * eb[(size_t)(s + 7) * H];
    }
    atomicAdd(&g_ectx[(size_t)b * H + h], ((a0 + a1) + (a2 + a3)) + ((a4 + a5) + (a6 + a7)));
}

// ============================================================
// K6: decoder attention + DH copy (champion, untouched)
// ============================================================
__global__ void k_dec(const float* __restrict__ pds, float* __restrict__ out) {
    extern __shared__ float sm[];
    float* pd = sm;
    float* sc = sm + T * H;
    float* at = sc + 64;
    int b = blockIdx.x, tid = threadIdx.x;
    for (int idx = tid; idx < T * H; idx += 512) {
        float v = pds[(size_t)b * T * H + idx];
        pd[idx] = v;
        int t = idx >> 9, hh = idx & 511;
        out[DH_OFF + ((size_t)b * (T + 1) + t) * H + hh] = v;
    }
    __syncthreads();
    int w = tid >> 5, lane = tid & 31;
    for (int t = w; t < T; t += 16) {
        float acc = 0.f;
#pragma unroll
        for (int q = 0; q < 16; q++)
            acc += g_hwd[(size_t)b * H + q * 32 + lane] * pd[t * H + q * 32 + lane];
        for (int o = 16; o; o >>= 1) acc += __shfl_xor_sync(0xffffffffu, acc, o);
        if (!lane) sc[t] = acc;
    }
    __syncthreads();
    if (tid < 32) {
        float s1 = (tid < T) ? sc[tid] : -1e30f;
        float s2 = (tid + 32 < T) ? sc[tid + 32] : -1e30f;
        float m = fmaxf(s1, s2);
        for (int o = 16; o; o >>= 1) m = fmaxf(m, __shfl_xor_sync(0xffffffffu, m, o));
        float e1 = (tid < T) ? __expf(s1 - m) : 0.f;
        float e2 = (tid + 32 < T) ? __expf(s2 - m) : 0.f;
        float sum = e1 + e2;
        for (int o = 16; o; o >>= 1) sum += __shfl_xor_sync(0xffffffffu, sum, o);
        if (tid < T) at[tid] = e1 / sum;
        if (tid + 32 < T) at[tid + 32] = e2 / sum;
    }
    __syncthreads();
    float acc = 0.f;
    for (int t = 0; t < T; t++) acc += at[t] * pd[t * H + tid];
    g_dctx[(size_t)b * H + tid] = acc;
}

// ============================================================
// K8: logits_h (champion, untouched)
// ============================================================
__global__ void k_outh(const float* __restrict__ Wo, const float* __restrict__ bo,
                       const float* __restrict__ ctrl) {
    __shared__ float Ws[8 * 128];
    __shared__ float Cs[32 * 129];
    int el = threadIdx.x >> 5, bl = threadIdx.x & 31;
    int e = blockIdx.x * 8 + el, bb = blockIdx.y * 32 + bl;
    float acc = 0.f;
    for (int kc = 0; kc < 1536; kc += 128) {
        __syncthreads();
        for (int idx = threadIdx.x; idx < 1024; idx += 256) {
            int ee = idx >> 7, k = idx & 127;
            Ws[idx] = Wo[(size_t)(blockIdx.x * 8 + ee) * CB + kc + k];
        }
        const float* src = (kc < 512) ? (g_h + kc)
                         : (kc < 1024) ? (g_ectx + kc - 512)
                                       : (g_dctx + kc - 1024);
        for (int idx = threadIdx.x; idx < 4096; idx += 256) {
            int b2 = idx >> 7, k = idx & 127;
            Cs[b2 * 129 + k] = src[(size_t)(blockIdx.y * 32 + b2) * H + k];
        }
        __syncthreads();
#pragma unroll 8
        for (int k = 0; k < 128; k++)
            acc += Ws[el * 128 + k] * Cs[bl * 129 + k];
    }
    acc += Wo[(size_t)e * CB + 1536] * ctrl[bb];
    g_lhb[(size_t)bb * E + e] = acc + bo[e];
}

// ============================================================
// K9: p_gen; zeros g_sumexp (champion, untouched)
// ============================================================
__global__ void k_pgen(const float* __restrict__ gw, const float* __restrict__ gb,
                       const float* __restrict__ ctrl, float* __restrict__ out) {
    int b = blockIdx.x * 8 + (threadIdx.x >> 5);
    int lane = threadIdx.x & 31;
    float acc = 0.f;
    for (int k = lane; k < H; k += 32) {
        acc += g_h[(size_t)b * H + k]    * gw[k];
        acc += g_ectx[(size_t)b * H + k] * gw[H + k];
        acc += g_dctx[(size_t)b * H + k] * gw[2 * H + k];
    }
    if (!lane) acc += ctrl[b] * gw[1536];
    for (int o = 16; o; o >>= 1) acc += __shfl_xor_sync(0xffffffffu, acc, o);
    if (!lane) {
        out[PG_OFF + b] = 1.f / (1.f + __expf(-(acc + gb[0])));
        g_sumexp[b] = 0.f;
    }
}

// ============================================================
// K10: vocab GEMM (champion, untouched — writes exp into p_vocab)
// ============================================================
__global__ void __launch_bounds__(512, 1)
k_outv_mma(const float* __restrict__ Wv, const float* __restrict__ bv,
           float* __restrict__ out) {
    extern __shared__ char smc[];
    __shared__ float s_bv[128];
    int tid = threadIdx.x;
    int vbase = blockIdx.x * 128;

    if (tid < 128) s_bv[tid] = (vbase + tid < V) ? bv[vbase + tid] : 0.f;

#pragma unroll
    for (int q = 0; q < 8; q++) {
        int idx = tid + q * 512;
        int r = idx >> 5;
        int c = (idx & 31) * 4;
        float4 w = make_float4(0.f, 0.f, 0.f, 0.f);
        if (vbase + r < V) w = *reinterpret_cast<const float4*>(Wv + (size_t)(vbase + r) * E + c);
        uint32_t h0, l0, h1, l1;
        split2(w.x, w.y, h0, l0);
        split2(w.z, w.w, h1, l1);
        size_t off = (size_t)(r * TSTR + c) * 2;
        *reinterpret_cast<uint2*>(smc + BHI_O + off) = make_uint2(h0, h1);
        *reinterpret_cast<uint2*>(smc + BLO_O + off) = make_uint2(l0, l1);
        float4 x = *reinterpret_cast<const float4*>(g_lhb + (size_t)r * E + c);
        split2(x.x, x.y, h0, l0);
        split2(x.z, x.w, h1, l1);
        *reinterpret_cast<uint2*>(smc + AHI_O + off) = make_uint2(h0, h1);
        *reinterpret_cast<uint2*>(smc + ALO_O + off) = make_uint2(l0, l1);
    }
    __syncthreads();

    int wid = tid >> 5, lane = tid & 31;
    int wm = wid >> 2, wn = wid & 3;
    int g = lane >> 2, t = lane & 3;

    float acc[2][4][4];
#pragma unroll
    for (int mi = 0; mi < 2; mi++)
#pragma unroll
        for (int ni = 0; ni < 4; ni++)
#pragma unroll
            for (int r = 0; r < 4; r++) acc[mi][ni][r] = 0.f;

    mma_chunk(smc, wm, wn, g, t, acc);
    __syncthreads();

    float* stage = reinterpret_cast<float*>(smc);
#pragma unroll
    for (int mi = 0; mi < 2; mi++) {
        int r0 = wm * 32 + mi * 16 + g;
#pragma unroll
        for (int ni = 0; ni < 4; ni++) {
            int n0 = wn * 32 + ni * 8 + 2 * t;
            bool v0 = (vbase + n0 < V), v1 = (vbase + n0 + 1 < V);
            float e00 = v0 ? __expf(acc[mi][ni][0] + s_bv[n0])     : 0.f;
            float e01 = v1 ? __expf(acc[mi][ni][1] + s_bv[n0 + 1]) : 0.f;
            float e10 = v0 ? __expf(acc[mi][ni][2] + s_bv[n0])     : 0.f;
            float e11 = v1 ? __expf(acc[mi][ni][3] + s_bv[n0 + 1]) : 0.f;
            stage[r0 * TSTR + n0]           = e00;
            stage[r0 * TSTR + n0 + 1]       = e01;
            stage[(r0 + 8) * TSTR + n0]     = e10;
            stage[(r0 + 8) * TSTR + n0 + 1] = e11;
        }
    }
    __syncthreads();

    if (tid < 256) {
        int row = tid >> 1, half = tid & 1;
        float lsum = 0.f;
        for (int c = half * 64; c < half * 64 + 64; c++) lsum += stage[row * TSTR + c];
        atomicAdd(&g_sumexp[row], lsum);
    }
    for (int idx = tid; idx < 128 * 128; idx += 512) {
        int b = idx >> 7, c = idx & 127;
        if (vbase + c < V)
            out[PV_OFF + (size_t)b * V + vbase + c] = stage[b * TSTR + c];
    }
}

// ============================================================
// K11: normalize p_vocab in place + p_final (champion)
// ============================================================
__global__ void k_pfinal(float* __restrict__ out) {
    int b = blockIdx.y;
    int v = (blockIdx.x * 256 + threadIdx.x) * 4;
    if (v >= VP) return;
    float pg = out[PG_OFF + b];
    if (v < V) {
        float4 u = *reinterpret_cast<const float4*>(out + PV_OFF + (size_t)b * V + v);
        float inv = __fdividef(1.f, g_sumexp[b]);
        float4 p = make_float4(u.x * inv, u.y * inv, u.z * inv, u.w * inv);
        *reinterpret_cast<float4*>(out + PV_OFF + (size_t)b * V + v) = p;
        *reinterpret_cast<float4*>(out + PF_OFF + (size_t)b * VP + v) =
            make_float4(p.x * pg, p.y * pg, p.z * pg, p.w * pg);
    } else {
        *reinterpret_cast<float4*>(out + PF_OFF + (size_t)b * VP + v) =
            make_float4(0.f, 0.f, 0.f, 0.f);
    }
}

// ============================================================
// K12: pointer scatter (champion)
// ============================================================
__global__ void k_scatter(const int* __restrict__ fiv, float* __restrict__ out) {
    int b = blockIdx.x, s = threadIdx.x;
    if (s < S) {
        float pg = out[PG_OFF + b];
        float val = (1.f - pg) * out[AD_OFF + (size_t)b * S + s];
        int idx = fiv[(size_t)b * S + s];
        atomicAdd(&out[PF_OFF + (size_t)b * VP + idx], val);
    }
}

// ============================================================
// launch — champion graph (NO t=0 side-stream kernels)
// ============================================================
extern "C" void kernel_launch(void* const* d_in, const int* in_sizes, int n_in,
                              void* d_out, int out_size) {
    const int*   tok    = (const int*)  d_in[0];
    const float* pds    = (const float*)d_in[1];
    const float* lh     = (const float*)d_in[2];
    const float* enc    = (const float*)d_in[3];
    const int*   fiv    = (const int*)  d_in[4];
    const float* pa     = (const float*)d_in[5];
    const float* ctrl   = (const float*)d_in[6];
    const float* emb    = (const float*)d_in[7];
    const float* W_ih   = (const float*)d_in[8];
    const float* W_hh   = (const float*)d_in[9];
    const float* b_ih   = (const float*)d_in[10];
    const float* b_hh   = (const float*)d_in[11];
    const float* w_h    = (const float*)d_in[12];
    const float* w_d    = (const float*)d_in[13];
    const float* gen_W  = (const float*)d_in[14];
    const float* gen_b  = (const float*)d_in[15];
    const float* outh_W = (const float*)d_in[16];
    const float* outh_b = (const float*)d_in[17];
    const float* outv_W = (const float*)d_in[18];
    const float* outv_b = (const float*)d_in[19];
    float* out = (float*)d_out;

    const int DEC_SMEM = (T * H + 128) * sizeof(float);
    cudaFuncSetAttribute(k_dec, cudaFuncAttributeMaxDynamicSharedMemorySize, DEC_SMEM);
    cudaFuncSetAttribute(k_outv_mma, cudaFuncAttributeMaxDynamicSharedMemorySize, MMA_DSMEM);

    cudaStream_t s1;
    cudaStreamCreateWithFlags(&s1, cudaStreamNonBlocking);
    cudaEvent_t evGates, evDec, evEctx, evPgen;
    cudaEventCreateWithFlags(&evGates, cudaEventDisableTiming);
    cudaEventCreateWithFlags(&evDec,   cudaEventDisableTiming);
    cudaEventCreateWithFlags(&evEctx,  cudaEventDisableTiming);
    cudaEventCreateWithFlags(&evPgen,  cudaEventDisableTiming);

    // main stream: GRU
    k_grugemm<<<dim3(J3H / 128, B / 16, 2), 256>>>(W_ih, W_hh, tok, emb, lh);
    k_gates<<<4 * B, 128>>>(lh, b_ih, b_hh, w_h, w_d, out);
    cudaEventRecord(evGates, 0);

    // side stream: decoder attention (fork AFTER chain start)
    cudaStreamWaitEvent(s1, evGates, 0);
    k_dec<<<B, 512, DEC_SMEM, s1>>>(pds, out);
    cudaEventRecord(evDec, s1);

    // main stream: encoder attention chain
    k_attsc<<<(B * S) / 8, 256>>>(enc);
    k_temporal<<<dim3(2, B), 256>>>(pa, out);
    k_ectx<<<dim3(10, B), 512>>>(enc, out);
    cudaEventRecord(evEctx, 0);

    // side stream: p_gen (needs ectx + dctx); zeros g_sumexp
    cudaStreamWaitEvent(s1, evEctx, 0);
    k_pgen<<<16, 256, 0, s1>>>(gen_W, gen_b, ctrl, out);
    cudaEventRecord(evPgen, s1);

    // main stream: output head, vocab GEMM, finals
    cudaStreamWaitEvent(0, evDec, 0);
    k_outh<<<dim3(16, 4), 256>>>(outh_W, outh_b, ctrl);
    cudaStreamWaitEvent(0, evPgen, 0);   // sumexp zeroed before outv atomics
    k_outv_mma<<<(V + 127) / 128, 512, MMA_DSMEM>>>(outv_W, outv_b, out);
    k_pfinal<<<dim3((VP / 4 + 255) / 256, B), 256>>>(out);
    k_scatter<<<B, 512>>>(fiv, out);

    cudaEventDestroy(evGates);
    cudaEventDestroy(evDec);
    cudaEventDestroy(evEctx);
    cudaEventDestroy(evPgen);
    cudaStreamDestroy(s1);
}

// round 13
// speedup vs baseline: 1.2568x; 1.0011x over previous
#include <cuda_runtime.h>
#include <cuda_bf16.h>
#include <math.h>
#include <stdint.h>

// Problem constants
#define B    128
#define S    400
#define T    50
#define H    512
#define E    128
#define V    50000
#define PADN 1000
#define J3H  1536
#define CB   1537
#define VP   51000

// ---- output layout (flattened tuple, float32) ----
#define PF_OFF  ((size_t)0)
#define PG_OFF  (PF_OFF + (size_t)B*VP)
#define PV_OFF  (PG_OFF + (size_t)B)
#define AD_OFF  (PV_OFF + (size_t)B*V)
#define DH_OFF  (AD_OFF + (size_t)B*S)
#define HH_OFF  (DH_OFF + (size_t)B*(T+1)*H)
#define NPA_OFF (HH_OFF + (size_t)B*H)

// ---- device scratch ----
__device__ __align__(16) float g_gx[B * J3H];
__device__ __align__(16) float g_gh[B * J3H];
__device__ __align__(16) float g_h[B * H];
__device__ __align__(16) float g_hw[B * H];
__device__ __align__(16) float g_hwd[B * H];
__device__ __align__(16) float g_att_scores[B * S];
__device__ __align__(16) float g_tu[B * S];     // unnormalized temporal
__device__ __align__(16) float g_sumT[B];
__device__ __align__(16) float g_ectx[B * H];
__device__ __align__(16) float g_dctx[B * H];
__device__ __align__(16) float g_lhb[B * E];    // logits_h [b][e]
__device__ __align__(16) float g_sumexp[B];

// ---- mma machinery (bf16 3-term split) ----
#define TSTR  132
#define TILEB (128 * TSTR * 2)
#define AHI_O 0
#define ALO_O (TILEB)
#define BHI_O (2 * TILEB)
#define BLO_O (3 * TILEB)
#define MMA_DSMEM (4 * TILEB)

__device__ __forceinline__ void split2(float a, float b, uint32_t& hv, uint32_t& lv) {
    __nv_bfloat162 hi = __float22bfloat162_rn(make_float2(a, b));
    float ra = a - __bfloat162float(hi.x);
    float rb = b - __bfloat162float(hi.y);
    __nv_bfloat162 lo = __float22bfloat162_rn(make_float2(ra, rb));
    hv = *reinterpret_cast<uint32_t*>(&hi);
    lv = *reinterpret_cast<uint32_t*>(&lo);
}
__device__ __forceinline__ void mma16816(float* c, const uint32_t* a, const uint32_t* b) {
    asm volatile(
        "mma.sync.aligned.m16n8k16.row.col.f32.bf16.bf16.f32 "
        "{%0,%1,%2,%3}, {%4,%5,%6,%7}, {%8,%9}, {%0,%1,%2,%3};"
        : "+f"(c[0]), "+f"(c[1]), "+f"(c[2]), "+f"(c[3])
        : "r"(a[0]), "r"(a[1]), "r"(a[2]), "r"(a[3]), "r"(b[0]), "r"(b[1]));
}
__device__ __forceinline__ void mma_chunk(char* smc, int wm, int wn, int g, int t,
                                          float acc[2][4][4]) {
#pragma unroll
    for (int term = 0; term < 3; term++) {
        int aoff = (term == 2) ? ALO_O : AHI_O;
        int boff = (term == 1) ? BLO_O : BHI_O;
#pragma unroll
        for (int ks = 0; ks < 8; ks++) {
            int kb = ks * 16;
            uint32_t af[2][4], bf[4][2];
#pragma unroll
            for (int mi = 0; mi < 2; mi++) {
                int row = wm * 32 + mi * 16 + g;
                size_t o = (size_t)aoff + (size_t)(row * TSTR + kb + 2 * t) * 2;
                af[mi][0] = *reinterpret_cast<const uint32_t*>(smc + o);
                af[mi][1] = *reinterpret_cast<const uint32_t*>(smc + o + 8 * TSTR * 2);
                af[mi][2] = *reinterpret_cast<const uint32_t*>(smc + o + 16);
                af[mi][3] = *reinterpret_cast<const uint32_t*>(smc + o + 8 * TSTR * 2 + 16);
            }
#pragma unroll
            for (int ni = 0; ni < 4; ni++) {
                int row = wn * 32 + ni * 8 + g;
                size_t o = (size_t)boff + (size_t)(row * TSTR + kb + 2 * t) * 2;
                bf[ni][0] = *reinterpret_cast<const uint32_t*>(smc + o);
                bf[ni][1] = *reinterpret_cast<const uint32_t*>(smc + o + 16);
            }
#pragma unroll
            for (int mi = 0; mi < 2; mi++)
#pragma unroll
                for (int ni = 0; ni < 4; ni++)
                    mma16816(acc[mi][ni], af[mi], bf[ni]);
        }
    }
}

// ============================================================
// K1: fused GRU GEMMs, smem-tiled (champion)
// ============================================================
__global__ void __launch_bounds__(256) k_grugemm(const float* __restrict__ Wih,
                                                 const float* __restrict__ Whh,
                                                 const int* __restrict__ tok,
                                                 const float* __restrict__ emb,
                                                 const float* __restrict__ lh) {
    int z = blockIdx.z;
    const float* W = z ? Whh : Wih;
    float* Cdst    = z ? g_gh : g_gx;
    int K = z ? H : E;

    __shared__ float Ws[128][33];
    __shared__ float Xs[32][17];
    __shared__ int stok[16];
    int tid = threadIdx.x;
    int j0 = blockIdx.x * 128, b0 = blockIdx.y * 16;
    if (tid < 16) stok[tid] = tok[b0 + tid];
    int tj = tid & 31, tb = tid >> 5;
    float acc[4][2];
#pragma unroll
    for (int q = 0; q < 4; q++) { acc[q][0] = 0.f; acc[q][1] = 0.f; }

    for (int kc = 0; kc < K; kc += 32) {
        __syncthreads();
#pragma unroll
        for (int q = 0; q < 4; q++) {
            int idx = tid + q * 256;
            int r = idx >> 3, c = (idx & 7) * 4;
            float4 w = *reinterpret_cast<const float4*>(W + (size_t)(j0 + r) * K + kc + c);
            Ws[r][c] = w.x; Ws[r][c + 1] = w.y; Ws[r][c + 2] = w.z; Ws[r][c + 3] = w.w;
        }
#pragma unroll
        for (int q = 0; q < 2; q++) {
            int e = tid + q * 256;
            int k = e >> 4, bb = e & 15;
            float xv;
            if (z == 0) xv = emb[(size_t)stok[bb] * E + kc + k];
            else        xv = lh[(size_t)(b0 + bb) * H + kc + k];
            Xs[k][bb] = xv;
        }
        __syncthreads();
#pragma unroll
        for (int k = 0; k < 32; k++) {
            float x0 = Xs[k][tb * 2], x1 = Xs[k][tb * 2 + 1];
#pragma unroll
            for (int q = 0; q < 4; q++) {
                float w = Ws[tj + q * 32][k];
                acc[q][0] += w * x0;
                acc[q][1] += w * x1;
            }
        }
    }
#pragma unroll
    for (int q = 0; q < 4; q++) {
        int j = j0 + tj + q * 32;
        Cdst[(size_t)(b0 + tb * 2) * J3H + j]     = acc[q][0];
        Cdst[(size_t)(b0 + tb * 2 + 1) * J3H + j] = acc[q][1];
    }
}

// ============================================================
// K2: GRU gates; zeros g_ectx and g_sumT (champion)
// ============================================================
__global__ void k_gates(const float* __restrict__ lh,
                        const float* __restrict__ b_ih,
                        const float* __restrict__ b_hh,
                        const float* __restrict__ w_h,
                        const float* __restrict__ w_d,
                        float* __restrict__ out) {
    int b = blockIdx.x >> 2;
    int i = ((blockIdx.x & 3) << 7) + threadIdx.x;
    if ((blockIdx.x & 3) == 0 && threadIdx.x == 0) g_sumT[b] = 0.f;
    float gx0 = g_gx[(size_t)b * J3H + i]         + b_ih[i];
    float gh0 = g_gh[(size_t)b * J3H + i]         + b_hh[i];
    float gx1 = g_gx[(size_t)b * J3H + H + i]     + b_ih[H + i];
    float gh1 = g_gh[(size_t)b * J3H + H + i]     + b_hh[H + i];
    float gx2 = g_gx[(size_t)b * J3H + 2 * H + i] + b_ih[2 * H + i];
    float gh2 = g_gh[(size_t)b * J3H + 2 * H + i] + b_hh[2 * H + i];
    float r = 1.f / (1.f + __expf(-(gx0 + gh0)));
    float z = 1.f / (1.f + __expf(-(gx1 + gh1)));
    float n = tanhf(gx2 + r * gh2);
    float hl = lh[(size_t)b * H + i];
    float h = (1.f - z) * n + z * hl;
    g_h[(size_t)b * H + i]   = h;
    g_hw[(size_t)b * H + i]  = h * w_h[i];
    g_hwd[(size_t)b * H + i] = h * w_d[i];
    g_ectx[(size_t)b * H + i] = 0.f;
    out[HH_OFF + (size_t)b * H + i] = h;
    out[DH_OFF + ((size_t)b * (T + 1) + T) * H + i] = h;
}

// ============================================================
// K3: att_scores — 2 s-rows per warp (MLP 8). grid (25, B) x 256.
// Warp w handles s = s0 + 2w, 2w+1; loads interleaved.
// ============================================================
__global__ void k_attsc(const float* __restrict__ enc) {
    int b = blockIdx.y;
    int w = threadIdx.x >> 5, lane = threadIdx.x & 31;
    int s = blockIdx.x * 16 + w * 2;
    const float4* e0 = reinterpret_cast<const float4*>(enc + ((size_t)b * S + s) * H);
    const float4* e1 = reinterpret_cast<const float4*>(enc + ((size_t)b * S + s + 1) * H);
    const float4* h4 = reinterpret_cast<const float4*>(g_hw + (size_t)b * H);
    float acc0 = 0.f, acc1 = 0.f;
#pragma unroll
    for (int q = 0; q < 4; q++) {
        int idx = q * 32 + lane;
        float4 a = e0[idx];
        float4 c = e1[idx];
        float4 hv = h4[idx];
        acc0 += a.x * hv.x + a.y * hv.y + a.z * hv.z + a.w * hv.w;
        acc1 += c.x * hv.x + c.y * hv.y + c.z * hv.z + c.w * hv.w;
    }
    for (int o = 16; o; o >>= 1) {
        acc0 += __shfl_xor_sync(0xffffffffu, acc0, o);
        acc1 += __shfl_xor_sync(0xffffffffu, acc1, o);
    }
    if (!lane) {
        g_att_scores[b * S + s]     = acc0;
        g_att_scores[b * S + s + 1] = acc1;
    }
}

// ============================================================
// K4: temporal (parallelized, champion)
// ============================================================
__global__ void k_temporal(const float* __restrict__ pa, float* __restrict__ out) {
    int b = blockIdx.y;
    int s = blockIdx.x * 200 + threadIdx.x;
    float tmp = 0.f;
    bool valid = (threadIdx.x < 200);
    if (valid) {
        float denom = 0.f;
        for (int t = 0; t < T; t++) {
            float v = pa[((size_t)b * T + t) * S + s];
            out[NPA_OFF + ((size_t)b * (T + 1) + t) * S + s] = v;
            denom += __expf(v);
        }
        float asc = g_att_scores[b * S + s];
        out[NPA_OFF + ((size_t)b * (T + 1) + T) * S + s] = asc;
        tmp = __expf(asc) / denom;
        g_tu[(size_t)b * S + s] = tmp;
    }
    float v = tmp;
    for (int o = 16; o; o >>= 1) v += __shfl_xor_sync(0xffffffffu, v, o);
    if ((threadIdx.x & 31) == 0 && v != 0.f) atomicAdd(&g_sumT[b], v);
}

// ============================================================
// K5: encoder_context + att_dist: grid (10, B), 40 s-rows (champion)
// ============================================================
__global__ void k_ectx(const float* __restrict__ enc, float* __restrict__ out) {
    __shared__ float att[40];
    int sy = blockIdx.x, b = blockIdx.y;
    int s0 = sy * 40;
    int h = threadIdx.x;
    float rsum = __fdividef(1.f, g_sumT[b]);
    if (h < 40) {
        float a = g_tu[(size_t)b * S + s0 + h] * rsum;
        att[h] = a;
        out[AD_OFF + (size_t)b * S + s0 + h] = a;
    }
    __syncthreads();
    float a0 = 0, a1 = 0, a2 = 0, a3 = 0, a4 = 0, a5 = 0, a6 = 0, a7 = 0;
    const float* eb = enc + ((size_t)b * S + s0) * H + h;
#pragma unroll
    for (int s = 0; s < 40; s += 8) {
        a0 += att[s + 0] * eb[(size_t)(s + 0) * H];
        a1 += att[s + 1] * eb[(size_t)(s + 1) * H];
        a2 += att[s + 2] * eb[(size_t)(s + 2) * H];
        a3 += att[s + 3] * eb[(size_t)(s + 3) * H];
        a4 += att[s + 4] * eb[(size_t)(s + 4) * H];
        a5 += att[s + 5] * eb[(size_t)(s + 5) * H];
        a6 += att[s + 6] * eb[(size_t)(s + 6) * H];
        a7 += att[s + 7] * eb[(size_t)(s + 7) * H];
    }
    atomicAdd(&g_ectx[(size_t)b * H + h], ((a0 + a1) + (a2 + a3)) + ((a4 + a5) + (a6 + a7)));
}

// ============================================================
// K6: decoder attention + DH copy (champion)
// ============================================================
__global__ void k_dec(const float* __restrict__ pds, float* __restrict__ out) {
    extern __shared__ float sm[];
    float* pd = sm;
    float* sc = sm + T * H;
    float* at = sc + 64;
    int b = blockIdx.x, tid = threadIdx.x;
    for (int idx = tid; idx < T * H; idx += 512) {
        float v = pds[(size_t)b * T * H + idx];
        pd[idx] = v;
        int t = idx >> 9, hh = idx & 511;
        out[DH_OFF + ((size_t)b * (T + 1) + t) * H + hh] = v;
    }
    __syncthreads();
    int w = tid >> 5, lane = tid & 31;
    for (int t = w; t < T; t += 16) {
        float acc = 0.f;
#pragma unroll
        for (int q = 0; q < 16; q++)
            acc += g_hwd[(size_t)b * H + q * 32 + lane] * pd[t * H + q * 32 + lane];
        for (int o = 16; o; o >>= 1) acc += __shfl_xor_sync(0xffffffffu, acc, o);
        if (!lane) sc[t] = acc;
    }
    __syncthreads();
    if (tid < 32) {
        float s1 = (tid < T) ? sc[tid] : -1e30f;
        float s2 = (tid + 32 < T) ? sc[tid + 32] : -1e30f;
        float m = fmaxf(s1, s2);
        for (int o = 16; o; o >>= 1) m = fmaxf(m, __shfl_xor_sync(0xffffffffu, m, o));
        float e1 = (tid < T) ? __expf(s1 - m) : 0.f;
        float e2 = (tid + 32 < T) ? __expf(s2 - m) : 0.f;
        float sum = e1 + e2;
        for (int o = 16; o; o >>= 1) sum += __shfl_xor_sync(0xffffffffu, sum, o);
        if (tid < T) at[tid] = e1 / sum;
        if (tid + 32 < T) at[tid + 32] = e2 / sum;
    }
    __syncthreads();
    float acc = 0.f;
    for (int t = 0; t < T; t++) acc += at[t] * pd[t * H + tid];
    g_dctx[(size_t)b * H + tid] = acc;
}

// ============================================================
// K8: logits_h (champion)
// ============================================================
__global__ void k_outh(const float* __restrict__ Wo, const float* __restrict__ bo,
                       const float* __restrict__ ctrl) {
    __shared__ float Ws[8 * 128];
    __shared__ float Cs[32 * 129];
    int el = threadIdx.x >> 5, bl = threadIdx.x & 31;
    int e = blockIdx.x * 8 + el, bb = blockIdx.y * 32 + bl;
    float acc = 0.f;
    for (int kc = 0; kc < 1536; kc += 128) {
        __syncthreads();
        for (int idx = threadIdx.x; idx < 1024; idx += 256) {
            int ee = idx >> 7, k = idx & 127;
            Ws[idx] = Wo[(size_t)(blockIdx.x * 8 + ee) * CB + kc + k];
        }
        const float* src = (kc < 512) ? (g_h + kc)
                         : (kc < 1024) ? (g_ectx + kc - 512)
                                       : (g_dctx + kc - 1024);
        for (int idx = threadIdx.x; idx < 4096; idx += 256) {
            int b2 = idx >> 7, k = idx & 127;
            Cs[b2 * 129 + k] = src[(size_t)(blockIdx.y * 32 + b2) * H + k];
        }
        __syncthreads();
#pragma unroll 8
        for (int k = 0; k < 128; k++)
            acc += Ws[el * 128 + k] * Cs[bl * 129 + k];
    }
    acc += Wo[(size_t)e * CB + 1536] * ctrl[bb];
    g_lhb[(size_t)bb * E + e] = acc + bo[e];
}

// ============================================================
// K9: p_gen; zeros g_sumexp (champion)
// ============================================================
__global__ void k_pgen(const float* __restrict__ gw, const float* __restrict__ gb,
                       const float* __restrict__ ctrl, float* __restrict__ out) {
    int b = blockIdx.x * 8 + (threadIdx.x >> 5);
    int lane = threadIdx.x & 31;
    float acc = 0.f;
    for (int k = lane; k < H; k += 32) {
        acc += g_h[(size_t)b * H + k]    * gw[k];
        acc += g_ectx[(size_t)b * H + k] * gw[H + k];
        acc += g_dctx[(size_t)b * H + k] * gw[2 * H + k];
    }
    if (!lane) acc += ctrl[b] * gw[1536];
    for (int o = 16; o; o >>= 1) acc += __shfl_xor_sync(0xffffffffu, acc, o);
    if (!lane) {
        out[PG_OFF + b] = 1.f / (1.f + __expf(-(acc + gb[0])));
        g_sumexp[b] = 0.f;
    }
}

// ============================================================
// K10: vocab GEMM (champion — writes exp into p_vocab)
// ============================================================
__global__ void __launch_bounds__(512, 1)
k_outv_mma(const float* __restrict__ Wv, const float* __restrict__ bv,
           float* __restrict__ out) {
    extern __shared__ char smc[];
    __shared__ float s_bv[128];
    int tid = threadIdx.x;
    int vbase = blockIdx.x * 128;

    if (tid < 128) s_bv[tid] = (vbase + tid < V) ? bv[vbase + tid] : 0.f;

#pragma unroll
    for (int q = 0; q < 8; q++) {
        int idx = tid + q * 512;
        int r = idx >> 5;
        int c = (idx & 31) * 4;
        float4 w = make_float4(0.f, 0.f, 0.f, 0.f);
        if (vbase + r < V) w = *reinterpret_cast<const float4*>(Wv + (size_t)(vbase + r) * E + c);
        uint32_t h0, l0, h1, l1;
        split2(w.x, w.y, h0, l0);
        split2(w.z, w.w, h1, l1);
        size_t off = (size_t)(r * TSTR + c) * 2;
        *reinterpret_cast<uint2*>(smc + BHI_O + off) = make_uint2(h0, h1);
        *reinterpret_cast<uint2*>(smc + BLO_O + off) = make_uint2(l0, l1);
        float4 x = *reinterpret_cast<const float4*>(g_lhb + (size_t)r * E + c);
        split2(x.x, x.y, h0, l0);
        split2(x.z, x.w, h1, l1);
        *reinterpret_cast<uint2*>(smc + AHI_O + off) = make_uint2(h0, h1);
        *reinterpret_cast<uint2*>(smc + ALO_O + off) = make_uint2(l0, l1);
    }
    __syncthreads();

    int wid = tid >> 5, lane = tid & 31;
    int wm = wid >> 2, wn = wid & 3;
    int g = lane >> 2, t = lane & 3;

    float acc[2][4][4];
#pragma unroll
    for (int mi = 0; mi < 2; mi++)
#pragma unroll
        for (int ni = 0; ni < 4; ni++)
#pragma unroll
            for (int r = 0; r < 4; r++) acc[mi][ni][r] = 0.f;

    mma_chunk(smc, wm, wn, g, t, acc);
    __syncthreads();

    float* stage = reinterpret_cast<float*>(smc);
#pragma unroll
    for (int mi = 0; mi < 2; mi++) {
        int r0 = wm * 32 + mi * 16 + g;
#pragma unroll
        for (int ni = 0; ni < 4; ni++) {
            int n0 = wn * 32 + ni * 8 + 2 * t;
            bool v0 = (vbase + n0 < V), v1 = (vbase + n0 + 1 < V);
            float e00 = v0 ? __expf(acc[mi][ni][0] + s_bv[n0])     : 0.f;
            float e01 = v1 ? __expf(acc[mi][ni][1] + s_bv[n0 + 1]) : 0.f;
            float e10 = v0 ? __expf(acc[mi][ni][2] + s_bv[n0])     : 0.f;
            float e11 = v1 ? __expf(acc[mi][ni][3] + s_bv[n0 + 1]) : 0.f;
            stage[r0 * TSTR + n0]           = e00;
            stage[r0 * TSTR + n0 + 1]       = e01;
            stage[(r0 + 8) * TSTR + n0]     = e10;
            stage[(r0 + 8) * TSTR + n0 + 1] = e11;
        }
    }
    __syncthreads();

    if (tid < 256) {
        int row = tid >> 1, half = tid & 1;
        float lsum = 0.f;
        for (int c = half * 64; c < half * 64 + 64; c++) lsum += stage[row * TSTR + c];
        atomicAdd(&g_sumexp[row], lsum);
    }
    for (int idx = tid; idx < 128 * 128; idx += 512) {
        int b = idx >> 7, c = idx & 127;
        if (vbase + c < V)
            out[PV_OFF + (size_t)b * V + vbase + c] = stage[b * TSTR + c];
    }
}

// ============================================================
// K11: normalize p_vocab in place + p_final (champion)
// ============================================================
__global__ void k_pfinal(float* __restrict__ out) {
    int b = blockIdx.y;
    int v = (blockIdx.x * 256 + threadIdx.x) * 4;
    if (v >= VP) return;
    float pg = out[PG_OFF + b];
    if (v < V) {
        float4 u = *reinterpret_cast<const float4*>(out + PV_OFF + (size_t)b * V + v);
        float inv = __fdividef(1.f, g_sumexp[b]);
        float4 p = make_float4(u.x * inv, u.y * inv, u.z * inv, u.w * inv);
        *reinterpret_cast<float4*>(out + PV_OFF + (size_t)b * V + v) = p;
        *reinterpret_cast<float4*>(out + PF_OFF + (size_t)b * VP + v) =
            make_float4(p.x * pg, p.y * pg, p.z * pg, p.w * pg);
    } else {
        *reinterpret_cast<float4*>(out + PF_OFF + (size_t)b * VP + v) =
            make_float4(0.f, 0.f, 0.f, 0.f);
    }
}

// ============================================================
// K12: pointer scatter (champion)
// ============================================================
__global__ void k_scatter(const int* __restrict__ fiv, float* __restrict__ out) {
    int b = blockIdx.x, s = threadIdx.x;
    if (s < S) {
        float pg = out[PG_OFF + b];
        float val = (1.f - pg) * out[AD_OFF + (size_t)b * S + s];
        int idx = fiv[(size_t)b * S + s];
        atomicAdd(&out[PF_OFF + (size_t)b * VP + idx], val);
    }
}

// ============================================================
// launch — champion graph (NO t=0 side-stream kernels)
// ============================================================
extern "C" void kernel_launch(void* const* d_in, const int* in_sizes, int n_in,
                              void* d_out, int out_size) {
    const int*   tok    = (const int*)  d_in[0];
    const float* pds    = (const float*)d_in[1];
    const float* lh     = (const float*)d_in[2];
    const float* enc    = (const float*)d_in[3];
    const int*   fiv    = (const int*)  d_in[4];
    const float* pa     = (const float*)d_in[5];
    const float* ctrl   = (const float*)d_in[6];
    const float* emb    = (const float*)d_in[7];
    const float* W_ih   = (const float*)d_in[8];
    const float* W_hh   = (const float*)d_in[9];
    const float* b_ih   = (const float*)d_in[10];
    const float* b_hh   = (const float*)d_in[11];
    const float* w_h    = (const float*)d_in[12];
    const float* w_d    = (const float*)d_in[13];
    const float* gen_W  = (const float*)d_in[14];
    const float* gen_b  = (const float*)d_in[15];
    const float* outh_W = (const float*)d_in[16];
    const float* outh_b = (const float*)d_in[17];
    const float* outv_W = (const float*)d_in[18];
    const float* outv_b = (const float*)d_in[19];
    float* out = (float*)d_out;

    const int DEC_SMEM = (T * H + 128) * sizeof(float);
    cudaFuncSetAttribute(k_dec, cudaFuncAttributeMaxDynamicSharedMemorySize, DEC_SMEM);
    cudaFuncSetAttribute(k_outv_mma, cudaFuncAttributeMaxDynamicSharedMemorySize, MMA_DSMEM);

    cudaStream_t s1;
    cudaStreamCreateWithFlags(&s1, cudaStreamNonBlocking);
    cudaEvent_t evGates, evDec, evEctx, evPgen;
    cudaEventCreateWithFlags(&evGates, cudaEventDisableTiming);
    cudaEventCreateWithFlags(&evDec,   cudaEventDisableTiming);
    cudaEventCreateWithFlags(&evEctx,  cudaEventDisableTiming);
    cudaEventCreateWithFlags(&evPgen,  cudaEventDisableTiming);

    // main stream: GRU
    k_grugemm<<<dim3(J3H / 128, B / 16, 2), 256>>>(W_ih, W_hh, tok, emb, lh);
    k_gates<<<4 * B, 128>>>(lh, b_ih, b_hh, w_h, w_d, out);
    cudaEventRecord(evGates, 0);

    // side stream: decoder attention (fork AFTER chain start)
    cudaStreamWaitEvent(s1, evGates, 0);
    k_dec<<<B, 512, DEC_SMEM, s1>>>(pds, out);
    cudaEventRecord(evDec, s1);

    // main stream: encoder attention chain
    k_attsc<<<dim3(S / 16, B), 256>>>(enc);
    k_temporal<<<dim3(2, B), 256>>>(pa, out);
    k_ectx<<<dim3(10, B), 512>>>(enc, out);
    cudaEventRecord(evEctx, 0);

    // side stream: p_gen (needs ectx + dctx); zeros g_sumexp
    cudaStreamWaitEvent(s1, evEctx, 0);
    k_pgen<<<16, 256, 0, s1>>>(gen_W, gen_b, ctrl, out);
    cudaEventRecord(evPgen, s1);

    // main stream: output head, vocab GEMM, finals
    cudaStreamWaitEvent(0, evDec, 0);
    k_outh<<<dim3(16, 4), 256>>>(outh_W, outh_b, ctrl);
    cudaStreamWaitEvent(0, evPgen, 0);   // sumexp zeroed before outv atomics
    k_outv_mma<<<(V + 127) / 128, 512, MMA_DSMEM>>>(outv_W, outv_b, out);
    k_pfinal<<<dim3((VP / 4 + 255) / 256, B), 256>>>(out);
    k_scatter<<<B, 512>>>(fiv, out);

    cudaEventDestroy(evGates);
    cudaEventDestroy(evDec);
    cudaEventDestroy(evEctx);
    cudaEventDestroy(evPgen);
    cudaStreamDestroy(s1);
}

// round 14
// speedup vs baseline: 1.4383x; 1.1444x over previous
#include <cuda_runtime.h>
#include <cuda_bf16.h>
#include <math.h>
#include <stdint.h>

// Problem constants
#define B    128
#define S    400
#define T    50
#define H    512
#define E    128
#define V    50000
#define PADN 1000
#define J3H  1536
#define CB   1537
#define VP   51000

// ---- output layout (flattened tuple, float32) ----
#define PF_OFF  ((size_t)0)
#define PG_OFF  (PF_OFF + (size_t)B*VP)
#define PV_OFF  (PG_OFF + (size_t)B)
#define AD_OFF  (PV_OFF + (size_t)B*V)
#define DH_OFF  (AD_OFF + (size_t)B*S)
#define HH_OFF  (DH_OFF + (size_t)B*(T+1)*H)
#define NPA_OFF (HH_OFF + (size_t)B*H)

// ---- device scratch ----
__device__ __align__(16) float g_gx[B * J3H];
__device__ __align__(16) float g_gh[B * J3H];
__device__ __align__(16) float g_h[B * H];
__device__ __align__(16) float g_hw[B * H];
__device__ __align__(16) float g_hwd[B * H];
__device__ __align__(16) float g_att_scores[B * S];
__device__ __align__(16) float g_tu[B * S];
__device__ __align__(16) float g_sumT[B];
__device__ __align__(16) float g_ectx[B * H];
__device__ __align__(16) float g_dctx[B * H];
__device__ __align__(16) float g_lhb[B * E];    // logits_h [b][e] (split-K accumulated)
__device__ __align__(16) float g_sumexp[B];

// ---- mma machinery (bf16 3-term split) ----
// TSTR = 136: fragment-load word bank = (4g + t) mod 32 — a perfect
// permutation over the warp's (g,t) lanes => conflict-free LDS.
#define TSTR  136
#define TILEB (128 * TSTR * 2)
#define AHI_O 0
#define ALO_O (TILEB)
#define BHI_O (2 * TILEB)
#define BLO_O (3 * TILEB)
#define MMA_DSMEM (4 * TILEB)

__device__ __forceinline__ void split2(float a, float b, uint32_t& hv, uint32_t& lv) {
    __nv_bfloat162 hi = __float22bfloat162_rn(make_float2(a, b));
    float ra = a - __bfloat162float(hi.x);
    float rb = b - __bfloat162float(hi.y);
    __nv_bfloat162 lo = __float22bfloat162_rn(make_float2(ra, rb));
    hv = *reinterpret_cast<uint32_t*>(&hi);
    lv = *reinterpret_cast<uint32_t*>(&lo);
}
__device__ __forceinline__ void mma16816(float* c, const uint32_t* a, const uint32_t* b) {
    asm volatile(
        "mma.sync.aligned.m16n8k16.row.col.f32.bf16.bf16.f32 "
        "{%0,%1,%2,%3}, {%4,%5,%6,%7}, {%8,%9}, {%0,%1,%2,%3};"
        : "+f"(c[0]), "+f"(c[1]), "+f"(c[2]), "+f"(c[3])
        : "r"(a[0]), "r"(a[1]), "r"(a[2]), "r"(a[3]), "r"(b[0]), "r"(b[1]));
}
__device__ __forceinline__ void mma_chunk(char* smc, int wm, int wn, int g, int t,
                                          float acc[2][4][4]) {
#pragma unroll
    for (int term = 0; term < 3; term++) {
        int aoff = (term == 2) ? ALO_O : AHI_O;
        int boff = (term == 1) ? BLO_O : BHI_O;
#pragma unroll
        for (int ks = 0; ks < 8; ks++) {
            int kb = ks * 16;
            uint32_t af[2][4], bf[4][2];
#pragma unroll
            for (int mi = 0; mi < 2; mi++) {
                int row = wm * 32 + mi * 16 + g;
                size_t o = (size_t)aoff + (size_t)(row * TSTR + kb + 2 * t) * 2;
                af[mi][0] = *reinterpret_cast<const uint32_t*>(smc + o);
                af[mi][1] = *reinterpret_cast<const uint32_t*>(smc + o + 8 * TSTR * 2);
                af[mi][2] = *reinterpret_cast<const uint32_t*>(smc + o + 16);
                af[mi][3] = *reinterpret_cast<const uint32_t*>(smc + o + 8 * TSTR * 2 + 16);
            }
#pragma unroll
            for (int ni = 0; ni < 4; ni++) {
                int row = wn * 32 + ni * 8 + g;
                size_t o = (size_t)boff + (size_t)(row * TSTR + kb + 2 * t) * 2;
                bf[ni][0] = *reinterpret_cast<const uint32_t*>(smc + o);
                bf[ni][1] = *reinterpret_cast<const uint32_t*>(smc + o + 16);
            }
#pragma unroll
            for (int mi = 0; mi < 2; mi++)
#pragma unroll
                for (int ni = 0; ni < 4; ni++)
                    mma16816(acc[mi][ni], af[mi], bf[ni]);
        }
    }
}

// ============================================================
// K1: fused GRU GEMMs, smem-tiled (champion)
// ============================================================
__global__ void __launch_bounds__(256) k_grugemm(const float* __restrict__ Wih,
                                                 const float* __restrict__ Whh,
                                                 const int* __restrict__ tok,
                                                 const float* __restrict__ emb,
                                                 const float* __restrict__ lh) {
    int z = blockIdx.z;
    const float* W = z ? Whh : Wih;
    float* Cdst    = z ? g_gh : g_gx;
    int K = z ? H : E;

    __shared__ float Ws[128][33];
    __shared__ float Xs[32][17];
    __shared__ int stok[16];
    int tid = threadIdx.x;
    int j0 = blockIdx.x * 128, b0 = blockIdx.y * 16;
    if (tid < 16) stok[tid] = tok[b0 + tid];
    int tj = tid & 31, tb = tid >> 5;
    float acc[4][2];
#pragma unroll
    for (int q = 0; q < 4; q++) { acc[q][0] = 0.f; acc[q][1] = 0.f; }

    for (int kc = 0; kc < K; kc += 32) {
        __syncthreads();
#pragma unroll
        for (int q = 0; q < 4; q++) {
            int idx = tid + q * 256;
            int r = idx >> 3, c = (idx & 7) * 4;
            float4 w = *reinterpret_cast<const float4*>(W + (size_t)(j0 + r) * K + kc + c);
            Ws[r][c] = w.x; Ws[r][c + 1] = w.y; Ws[r][c + 2] = w.z; Ws[r][c + 3] = w.w;
        }
#pragma unroll
        for (int q = 0; q < 2; q++) {
            int e = tid + q * 256;
            int k = e >> 4, bb = e & 15;
            float xv;
            if (z == 0) xv = emb[(size_t)stok[bb] * E + kc + k];
            else        xv = lh[(size_t)(b0 + bb) * H + kc + k];
            Xs[k][bb] = xv;
        }
        __syncthreads();
#pragma unroll
        for (int k = 0; k < 32; k++) {
            float x0 = Xs[k][tb * 2], x1 = Xs[k][tb * 2 + 1];
#pragma unroll
            for (int q = 0; q < 4; q++) {
                float w = Ws[tj + q * 32][k];
                acc[q][0] += w * x0;
                acc[q][1] += w * x1;
            }
        }
    }
#pragma unroll
    for (int q = 0; q < 4; q++) {
        int j = j0 + tj + q * 32;
        Cdst[(size_t)(b0 + tb * 2) * J3H + j]     = acc[q][0];
        Cdst[(size_t)(b0 + tb * 2 + 1) * J3H + j] = acc[q][1];
    }
}

// ============================================================
// K2: GRU gates; zeros g_ectx, g_sumT, g_lhb (champion + lhb zero)
// ============================================================
__global__ void k_gates(const float* __restrict__ lh,
                        const float* __restrict__ b_ih,
                        const float* __restrict__ b_hh,
                        const float* __restrict__ w_h,
                        const float* __restrict__ w_d,
                        float* __restrict__ out) {
    int b = blockIdx.x >> 2;
    int i = ((blockIdx.x & 3) << 7) + threadIdx.x;
    if ((blockIdx.x & 3) == 0) {
        if (threadIdx.x == 0) g_sumT[b] = 0.f;
        g_lhb[(size_t)b * E + threadIdx.x] = 0.f;   // 128 threads cover E
    }
    float gx0 = g_gx[(size_t)b * J3H + i]         + b_ih[i];
    float gh0 = g_gh[(size_t)b * J3H + i]         + b_hh[i];
    float gx1 = g_gx[(size_t)b * J3H + H + i]     + b_ih[H + i];
    float gh1 = g_gh[(size_t)b * J3H + H + i]     + b_hh[H + i];
    float gx2 = g_gx[(size_t)b * J3H + 2 * H + i] + b_ih[2 * H + i];
    float gh2 = g_gh[(size_t)b * J3H + 2 * H + i] + b_hh[2 * H + i];
    float r = 1.f / (1.f + __expf(-(gx0 + gh0)));
    float z = 1.f / (1.f + __expf(-(gx1 + gh1)));
    float n = tanhf(gx2 + r * gh2);
    float hl = lh[(size_t)b * H + i];
    float h = (1.f - z) * n + z * hl;
    g_h[(size_t)b * H + i]   = h;
    g_hw[(size_t)b * H + i]  = h * w_h[i];
    g_hwd[(size_t)b * H + i] = h * w_d[i];
    g_ectx[(size_t)b * H + i] = 0.f;
    out[HH_OFF + (size_t)b * H + i] = h;
    out[DH_OFF + ((size_t)b * (T + 1) + T) * H + i] = h;
}

// ============================================================
// K3: att_scores — 2 s-rows per warp (champion)
// ============================================================
__global__ void k_attsc(const float* __restrict__ enc) {
    int b = blockIdx.y;
    int w = threadIdx.x >> 5, lane = threadIdx.x & 31;
    int s = blockIdx.x * 16 + w * 2;
    const float4* e0 = reinterpret_cast<const float4*>(enc + ((size_t)b * S + s) * H);
    const float4* e1 = reinterpret_cast<const float4*>(enc + ((size_t)b * S + s + 1) * H);
    const float4* h4 = reinterpret_cast<const float4*>(g_hw + (size_t)b * H);
    float acc0 = 0.f, acc1 = 0.f;
#pragma unroll
    for (int q = 0; q < 4; q++) {
        int idx = q * 32 + lane;
        float4 a = e0[idx];
        float4 c = e1[idx];
        float4 hv = h4[idx];
        acc0 += a.x * hv.x + a.y * hv.y + a.z * hv.z + a.w * hv.w;
        acc1 += c.x * hv.x + c.y * hv.y + c.z * hv.z + c.w * hv.w;
    }
    for (int o = 16; o; o >>= 1) {
        acc0 += __shfl_xor_sync(0xffffffffu, acc0, o);
        acc1 += __shfl_xor_sync(0xffffffffu, acc1, o);
    }
    if (!lane) {
        g_att_scores[b * S + s]     = acc0;
        g_att_scores[b * S + s + 1] = acc1;
    }
}

// ============================================================
// K4: temporal (champion)
// ============================================================
__global__ void k_temporal(const float* __restrict__ pa, float* __restrict__ out) {
    int b = blockIdx.y;
    int s = blockIdx.x * 200 + threadIdx.x;
    float tmp = 0.f;
    bool valid = (threadIdx.x < 200);
    if (valid) {
        float denom = 0.f;
        for (int t = 0; t < T; t++) {
            float v = pa[((size_t)b * T + t) * S + s];
            out[NPA_OFF + ((size_t)b * (T + 1) + t) * S + s] = v;
            denom += __expf(v);
        }
        float asc = g_att_scores[b * S + s];
        out[NPA_OFF + ((size_t)b * (T + 1) + T) * S + s] = asc;
        tmp = __expf(asc) / denom;
        g_tu[(size_t)b * S + s] = tmp;
    }
    float v = tmp;
    for (int o = 16; o; o >>= 1) v += __shfl_xor_sync(0xffffffffu, v, o);
    if ((threadIdx.x & 31) == 0 && v != 0.f) atomicAdd(&g_sumT[b], v);
}

// ============================================================
// K5: encoder_context + att_dist (champion)
// ============================================================
__global__ void k_ectx(const float* __restrict__ enc, float* __restrict__ out) {
    __shared__ float att[40];
    int sy = blockIdx.x, b = blockIdx.y;
    int s0 = sy * 40;
    int h = threadIdx.x;
    float rsum = __fdividef(1.f, g_sumT[b]);
    if (h < 40) {
        float a = g_tu[(size_t)b * S + s0 + h] * rsum;
        att[h] = a;
        out[AD_OFF + (size_t)b * S + s0 + h] = a;
    }
    __syncthreads();
    float a0 = 0, a1 = 0, a2 = 0, a3 = 0, a4 = 0, a5 = 0, a6 = 0, a7 = 0;
    const float* eb = enc + ((size_t)b * S + s0) * H + h;
#pragma unroll
    for (int s = 0; s < 40; s += 8) {
        a0 += att[s + 0] * eb[(size_t)(s + 0) * H];
        a1 += att[s + 1] * eb[(size_t)(s + 1) * H];
        a2 += att[s + 2] * eb[(size_t)(s + 2) * H];
        a3 += att[s + 3] * eb[(size_t)(s + 3) * H];
        a4 += att[s + 4] * eb[(size_t)(s + 4) * H];
        a5 += att[s + 5] * eb[(size_t)(s + 5) * H];
        a6 += att[s + 6] * eb[(size_t)(s + 6) * H];
        a7 += att[s + 7] * eb[(size_t)(s + 7) * H];
    }
    atomicAdd(&g_ectx[(size_t)b * H + h], ((a0 + a1) + (a2 + a3)) + ((a4 + a5) + (a6 + a7)));
}

// ============================================================
// K6: decoder attention + DH copy (champion)
// ============================================================
__global__ void k_dec(const float* __restrict__ pds, float* __restrict__ out) {
    extern __shared__ float sm[];
    float* pd = sm;
    float* sc = sm + T * H;
    float* at = sc + 64;
    int b = blockIdx.x, tid = threadIdx.x;
    for (int idx = tid; idx < T * H; idx += 512) {
        float v = pds[(size_t)b * T * H + idx];
        pd[idx] = v;
        int t = idx >> 9, hh = idx & 511;
        out[DH_OFF + ((size_t)b * (T + 1) + t) * H + hh] = v;
    }
    __syncthreads();
    int w = tid >> 5, lane = tid & 31;
    for (int t = w; t < T; t += 16) {
        float acc = 0.f;
#pragma unroll
        for (int q = 0; q < 16; q++)
            acc += g_hwd[(size_t)b * H + q * 32 + lane] * pd[t * H + q * 32 + lane];
        for (int o = 16; o; o >>= 1) acc += __shfl_xor_sync(0xffffffffu, acc, o);
        if (!lane) sc[t] = acc;
    }
    __syncthreads();
    if (tid < 32) {
        float s1 = (tid < T) ? sc[tid] : -1e30f;
        float s2 = (tid + 32 < T) ? sc[tid + 32] : -1e30f;
        float m = fmaxf(s1, s2);
        for (int o = 16; o; o >>= 1) m = fmaxf(m, __shfl_xor_sync(0xffffffffu, m, o));
        float e1 = (tid < T) ? __expf(s1 - m) : 0.f;
        float e2 = (tid + 32 < T) ? __expf(s2 - m) : 0.f;
        float sum = e1 + e2;
        for (int o = 16; o; o >>= 1) sum += __shfl_xor_sync(0xffffffffu, sum, o);
        if (tid < T) at[tid] = e1 / sum;
        if (tid + 32 < T) at[tid + 32] = e2 / sum;
    }
    __syncthreads();
    float acc = 0.f;
    for (int t = 0; t < T; t++) acc += at[t] * pd[t * H + tid];
    g_dctx[(size_t)b * H + tid] = acc;
}

// ============================================================
// K8: logits_h, split-K: grid (16, 4, 2). z=0 -> k [0,768),
// z=1 -> k [768,1536) + ctrl + bias. atomicAdd into zeroed g_lhb.
// ============================================================
__global__ void k_outh(const float* __restrict__ Wo, const float* __restrict__ bo,
                       const float* __restrict__ ctrl) {
    __shared__ float Ws[8 * 128];
    __shared__ float Cs[32 * 129];
    int el = threadIdx.x >> 5, bl = threadIdx.x & 31;
    int e = blockIdx.x * 8 + el, bb = blockIdx.y * 32 + bl;
    int kbase = blockIdx.z * 768;
    float acc = 0.f;
    for (int kq = 0; kq < 768; kq += 128) {
        int kc = kbase + kq;
        __syncthreads();
        for (int idx = threadIdx.x; idx < 1024; idx += 256) {
            int ee = idx >> 7, k = idx & 127;
            Ws[idx] = Wo[(size_t)(blockIdx.x * 8 + ee) * CB + kc + k];
        }
        const float* src = (kc < 512) ? (g_h + kc)
                         : (kc < 1024) ? (g_ectx + kc - 512)
                                       : (g_dctx + kc - 1024);
        for (int idx = threadIdx.x; idx < 4096; idx += 256) {
            int b2 = idx >> 7, k = idx & 127;
            Cs[b2 * 129 + k] = src[(size_t)(blockIdx.y * 32 + b2) * H + k];
        }
        __syncthreads();
#pragma unroll 8
        for (int k = 0; k < 128; k++)
            acc += Ws[el * 128 + k] * Cs[bl * 129 + k];
    }
    if (blockIdx.z == 1)
        acc += Wo[(size_t)e * CB + 1536] * ctrl[bb] + bo[e];
    atomicAdd(&g_lhb[(size_t)bb * E + e], acc);
}

// ============================================================
// K9: p_gen; zeros g_sumexp (champion)
// ============================================================
__global__ void k_pgen(const float* __restrict__ gw, const float* __restrict__ gb,
                       const float* __restrict__ ctrl, float* __restrict__ out) {
    int b = blockIdx.x * 8 + (threadIdx.x >> 5);
    int lane = threadIdx.x & 31;
    float acc = 0.f;
    for (int k = lane; k < H; k += 32) {
        acc += g_h[(size_t)b * H + k]    * gw[k];
        acc += g_ectx[(size_t)b * H + k] * gw[H + k];
        acc += g_dctx[(size_t)b * H + k] * gw[2 * H + k];
    }
    if (!lane) acc += ctrl[b] * gw[1536];
    for (int o = 16; o; o >>= 1) acc += __shfl_xor_sync(0xffffffffu, acc, o);
    if (!lane) {
        out[PG_OFF + b] = 1.f / (1.f + __expf(-(acc + gb[0])));
        g_sumexp[b] = 0.f;
    }
}

// ============================================================
// K10: vocab GEMM (conflict-free TSTR=136; writes exp into p_vocab)
// ============================================================
__global__ void __launch_bounds__(512, 1)
k_outv_mma(const float* __restrict__ Wv, const float* __restrict__ bv,
           float* __restrict__ out) {
    extern __shared__ char smc[];
    __shared__ float s_bv[128];
    int tid = threadIdx.x;
    int vbase = blockIdx.x * 128;

    if (tid < 128) s_bv[tid] = (vbase + tid < V) ? bv[vbase + tid] : 0.f;

#pragma unroll
    for (int q = 0; q < 8; q++) {
        int idx = tid + q * 512;
        int r = idx >> 5;
        int c = (idx & 31) * 4;
        float4 w = make_float4(0.f, 0.f, 0.f, 0.f);
        if (vbase + r < V) w = *reinterpret_cast<const float4*>(Wv + (size_t)(vbase + r) * E + c);
        uint32_t h0, l0, h1, l1;
        split2(w.x, w.y, h0, l0);
        split2(w.z, w.w, h1, l1);
        size_t off = (size_t)(r * TSTR + c) * 2;
        *reinterpret_cast<uint2*>(smc + BHI_O + off) = make_uint2(h0, h1);
        *reinterpret_cast<uint2*>(smc + BLO_O + off) = make_uint2(l0, l1);
        float4 x = *reinterpret_cast<const float4*>(g_lhb + (size_t)r * E + c);
        split2(x.x, x.y, h0, l0);
        split2(x.z, x.w, h1, l1);
        *reinterpret_cast<uint2*>(smc + AHI_O + off) = make_uint2(h0, h1);
        *reinterpret_cast<uint2*>(smc + ALO_O + off) = make_uint2(l0, l1);
    }
    __syncthreads();

    int wid = tid >> 5, lane = tid & 31;
    int wm = wid >> 2, wn = wid & 3;
    int g = lane >> 2, t = lane & 3;

    float acc[2][4][4];
#pragma unroll
    for (int mi = 0; mi < 2; mi++)
#pragma unroll
        for (int ni = 0; ni < 4; ni++)
#pragma unroll
            for (int r = 0; r < 4; r++) acc[mi][ni][r] = 0.f;

    mma_chunk(smc, wm, wn, g, t, acc);
    __syncthreads();

    float* stage = reinterpret_cast<float*>(smc);
#pragma unroll
    for (int mi = 0; mi < 2; mi++) {
        int r0 = wm * 32 + mi * 16 + g;
#pragma unroll
        for (int ni = 0; ni < 4; ni++) {
            int n0 = wn * 32 + ni * 8 + 2 * t;
            bool v0 = (vbase + n0 < V), v1 = (vbase + n0 + 1 < V);
            float e00 = v0 ? __expf(acc[mi][ni][0] + s_bv[n0])     : 0.f;
            float e01 = v1 ? __expf(acc[mi][ni][1] + s_bv[n0 + 1]) : 0.f;
            float e10 = v0 ? __expf(acc[mi][ni][2] + s_bv[n0])     : 0.f;
            float e11 = v1 ? __expf(acc[mi][ni][3] + s_bv[n0 + 1]) : 0.f;
            stage[r0 * TSTR + n0]           = e00;
            stage[r0 * TSTR + n0 + 1]       = e01;
            stage[(r0 + 8) * TSTR + n0]     = e10;
            stage[(r0 + 8) * TSTR + n0 + 1] = e11;
        }
    }
    __syncthreads();

    if (tid < 256) {
        int row = tid >> 1, half = tid & 1;
        float lsum = 0.f;
        for (int c = half * 64; c < half * 64 + 64; c++) lsum += stage[row * TSTR + c];
        atomicAdd(&g_sumexp[row], lsum);
    }
    for (int idx = tid; idx < 128 * 128; idx += 512) {
        int b = idx >> 7, c = idx & 127;
        if (vbase + c < V)
            out[PV_OFF + (size_t)b * V + vbase + c] = stage[b * TSTR + c];
    }
}

// ============================================================
// K11: normalize p_vocab in place + p_final (champion)
// ============================================================
__global__ void k_pfinal(float* __restrict__ out) {
    int b = blockIdx.y;
    int v = (blockIdx.x * 256 + threadIdx.x) * 4;
    if (v >= VP) return;
    float pg = out[PG_OFF + b];
    if (v < V) {
        float4 u = *reinterpret_cast<const float4*>(out + PV_OFF + (size_t)b * V + v);
        float inv = __fdividef(1.f, g_sumexp[b]);
        float4 p = make_float4(u.x * inv, u.y * inv, u.z * inv, u.w * inv);
        *reinterpret_cast<float4*>(out + PV_OFF + (size_t)b * V + v) = p;
        *reinterpret_cast<float4*>(out + PF_OFF + (size_t)b * VP + v) =
            make_float4(p.x * pg, p.y * pg, p.z * pg, p.w * pg);
    } else {
        *reinterpret_cast<float4*>(out + PF_OFF + (size_t)b * VP + v) =
            make_float4(0.f, 0.f, 0.f, 0.f);
    }
}

// ============================================================
// K12: pointer scatter (champion)
// ============================================================
__global__ void k_scatter(const int* __restrict__ fiv, float* __restrict__ out) {
    int b = blockIdx.x, s = threadIdx.x;
    if (s < S) {
        float pg = out[PG_OFF + b];
        float val = (1.f - pg) * out[AD_OFF + (size_t)b * S + s];
        int idx = fiv[(size_t)b * S + s];
        atomicAdd(&out[PF_OFF + (size_t)b * VP + idx], val);
    }
}

// ============================================================
// launch — champion graph
// ============================================================
extern "C" void kernel_launch(void* const* d_in, const int* in_sizes, int n_in,
                              void* d_out, int out_size) {
    const int*   tok    = (const int*)  d_in[0];
    const float* pds    = (const float*)d_in[1];
    const float* lh     = (const float*)d_in[2];
    const float* enc    = (const float*)d_in[3];
    const int*   fiv    = (const int*)  d_in[4];
    const float* pa     = (const float*)d_in[5];
    const float* ctrl   = (const float*)d_in[6];
    const float* emb    = (const float*)d_in[7];
    const float* W_ih   = (const float*)d_in[8];
    const float* W_hh   = (const float*)d_in[9];
    const float* b_ih   = (const float*)d_in[10];
    const float* b_hh   = (const float*)d_in[11];
    const float* w_h    = (const float*)d_in[12];
    const float* w_d    = (const float*)d_in[13];
    const float* gen_W  = (const float*)d_in[14];
    const float* gen_b  = (const float*)d_in[15];
    const float* outh_W = (const float*)d_in[16];
    const float* outh_b = (const float*)d_in[17];
    const float* outv_W = (const float*)d_in[18];
    const float* outv_b = (const float*)d_in[19];
    float* out = (float*)d_out;

    const int DEC_SMEM = (T * H + 128) * sizeof(float);
    cudaFuncSetAttribute(k_dec, cudaFuncAttributeMaxDynamicSharedMemorySize, DEC_SMEM);
    cudaFuncSetAttribute(k_outv_mma, cudaFuncAttributeMaxDynamicSharedMemorySize, MMA_DSMEM);

    cudaStream_t s1;
    cudaStreamCreateWithFlags(&s1, cudaStreamNonBlocking);
    cudaEvent_t evGates, evDec, evEctx, evPgen;
    cudaEventCreateWithFlags(&evGates, cudaEventDisableTiming);
    cudaEventCreateWithFlags(&evDec,   cudaEventDisableTiming);
    cudaEventCreateWithFlags(&evEctx,  cudaEventDisableTiming);
    cudaEventCreateWithFlags(&evPgen,  cudaEventDisableTiming);

    // main stream: GRU
    k_grugemm<<<dim3(J3H / 128, B / 16, 2), 256>>>(W_ih, W_hh, tok, emb, lh);
    k_gates<<<4 * B, 128>>>(lh, b_ih, b_hh, w_h, w_d, out);
    cudaEventRecord(evGates, 0);

    // side stream: decoder attention (fork AFTER chain start)
    cudaStreamWaitEvent(s1, evGates, 0);
    k_dec<<<B, 512, DEC_SMEM, s1>>>(pds, out);
    cudaEventRecord(evDec, s1);

    // main stream: encoder attention chain
    k_attsc<<<dim3(S / 16, B), 256>>>(enc);
    k_temporal<<<dim3(2, B), 256>>>(pa, out);
    k_ectx<<<dim3(10, B), 512>>>(enc, out);
    cudaEventRecord(evEctx, 0);

    // side stream: p_gen (needs ectx + dctx); zeros g_sumexp
    cudaStreamWaitEvent(s1, evEctx, 0);
    k_pgen<<<16, 256, 0, s1>>>(gen_W, gen_b, ctrl, out);
    cudaEventRecord(evPgen, s1);

    // main stream: output head (split-K), vocab GEMM, finals
    cudaStreamWaitEvent(0, evDec, 0);
    k_outh<<<dim3(16, 4, 2), 256>>>(outh_W, outh_b, ctrl);
    cudaStreamWaitEvent(0, evPgen, 0);   // sumexp zeroed before outv atomics
    k_outv_mma<<<(V + 127) / 128, 512, MMA_DSMEM>>>(outv_W, outv_b, out);
    k_pfinal<<<dim3((VP / 4 + 255) / 256, B), 256>>>(out);
    k_scatter<<<B, 512>>>(fiv, out);

    cudaEventDestroy(evGates);
    cudaEventDestroy(evDec);
    cudaEventDestroy(evEctx);
    cudaEventDestroy(evPgen);
    cudaStreamDestroy(s1);
}

// round 15
// speedup vs baseline: 1.4680x; 1.0207x over previous
#include <cuda_runtime.h>
#include <cuda_bf16.h>
#include <math.h>
#include <stdint.h>

// Problem constants
#define B    128
#define S    400
#define T    50
#define H    512
#define E    128
#define V    50000
#define PADN 1000
#define J3H  1536
#define CB   1537
#define VP   51000

// ---- output layout (flattened tuple, float32) ----
#define PF_OFF  ((size_t)0)
#define PG_OFF  (PF_OFF + (size_t)B*VP)
#define PV_OFF  (PG_OFF + (size_t)B)
#define AD_OFF  (PV_OFF + (size_t)B*V)
#define DH_OFF  (AD_OFF + (size_t)B*S)
#define HH_OFF  (DH_OFF + (size_t)B*(T+1)*H)
#define NPA_OFF (HH_OFF + (size_t)B*H)

// ---- device scratch ----
__device__ __align__(16) float g_gx[B * J3H];
__device__ __align__(16) float g_gh[B * J3H];
__device__ __align__(16) float g_h[B * H];
__device__ __align__(16) float g_hw[B * H];
__device__ __align__(16) float g_hwd[B * H];
__device__ __align__(16) float g_att_scores[B * S];
__device__ __align__(16) float g_tu[B * S];
__device__ __align__(16) float g_sumT[B];
__device__ __align__(16) float g_ectx[B * H];
__device__ __align__(16) float g_dctx[B * H];
__device__ __align__(16) float g_lhb[B * E];    // logits_h (split-K accumulated)
__device__ __align__(16) float g_sumexp[B];

// ---- mma machinery (bf16 3-term split), conflict-free TSTR=136 ----
// 64-row B tiles for 2 CTAs/SM occupancy.
#define TSTR  136
#define ATILE (128 * TSTR * 2)          // A: 128 rows
#define BTILE (64 * TSTR * 2)           // B: 64 rows
#define AHI_O 0
#define ALO_O (ATILE)
#define BHI_O (2 * ATILE)
#define BLO_O (2 * ATILE + BTILE)
#define MMA_DSMEM (2 * ATILE + 2 * BTILE)   // 104448 B
#define TST2  68                         // epilogue stage stride (64+4)

__device__ __forceinline__ void split2(float a, float b, uint32_t& hv, uint32_t& lv) {
    __nv_bfloat162 hi = __float22bfloat162_rn(make_float2(a, b));
    float ra = a - __bfloat162float(hi.x);
    float rb = b - __bfloat162float(hi.y);
    __nv_bfloat162 lo = __float22bfloat162_rn(make_float2(ra, rb));
    hv = *reinterpret_cast<uint32_t*>(&hi);
    lv = *reinterpret_cast<uint32_t*>(&lo);
}
__device__ __forceinline__ void mma16816(float* c, const uint32_t* a, const uint32_t* b) {
    asm volatile(
        "mma.sync.aligned.m16n8k16.row.col.f32.bf16.bf16.f32 "
        "{%0,%1,%2,%3}, {%4,%5,%6,%7}, {%8,%9}, {%0,%1,%2,%3};"
        : "+f"(c[0]), "+f"(c[1]), "+f"(c[2]), "+f"(c[3])
        : "r"(a[0]), "r"(a[1]), "r"(a[2]), "r"(a[3]), "r"(b[0]), "r"(b[1]));
}
__device__ __forceinline__ void mma_chunk(char* smc, int wm, int wn, int g, int t,
                                          float acc[2][4][4]) {
#pragma unroll
    for (int term = 0; term < 3; term++) {
        int aoff = (term == 2) ? ALO_O : AHI_O;
        int boff = (term == 1) ? BLO_O : BHI_O;
#pragma unroll
        for (int ks = 0; ks < 8; ks++) {
            int kb = ks * 16;
            uint32_t af[2][4], bf[4][2];
#pragma unroll
            for (int mi = 0; mi < 2; mi++) {
                int row = wm * 32 + mi * 16 + g;
                size_t o = (size_t)aoff + (size_t)(row * TSTR + kb + 2 * t) * 2;
                af[mi][0] = *reinterpret_cast<const uint32_t*>(smc + o);
                af[mi][1] = *reinterpret_cast<const uint32_t*>(smc + o + 8 * TSTR * 2);
                af[mi][2] = *reinterpret_cast<const uint32_t*>(smc + o + 16);
                af[mi][3] = *reinterpret_cast<const uint32_t*>(smc + o + 8 * TSTR * 2 + 16);
            }
#pragma unroll
            for (int ni = 0; ni < 4; ni++) {
                int row = wn * 32 + ni * 8 + g;
                size_t o = (size_t)boff + (size_t)(row * TSTR + kb + 2 * t) * 2;
                bf[ni][0] = *reinterpret_cast<const uint32_t*>(smc + o);
                bf[ni][1] = *reinterpret_cast<const uint32_t*>(smc + o + 16);
            }
#pragma unroll
            for (int mi = 0; mi < 2; mi++)
#pragma unroll
                for (int ni = 0; ni < 4; ni++)
                    mma16816(acc[mi][ni], af[mi], bf[ni]);
        }
    }
}

// ============================================================
// K1: fused GRU GEMMs (champion)
// ============================================================
__global__ void __launch_bounds__(256) k_grugemm(const float* __restrict__ Wih,
                                                 const float* __restrict__ Whh,
                                                 const int* __restrict__ tok,
                                                 const float* __restrict__ emb,
                                                 const float* __restrict__ lh) {
    int z = blockIdx.z;
    const float* W = z ? Whh : Wih;
    float* Cdst    = z ? g_gh : g_gx;
    int K = z ? H : E;

    __shared__ float Ws[128][33];
    __shared__ float Xs[32][17];
    __shared__ int stok[16];
    int tid = threadIdx.x;
    int j0 = blockIdx.x * 128, b0 = blockIdx.y * 16;
    if (tid < 16) stok[tid] = tok[b0 + tid];
    int tj = tid & 31, tb = tid >> 5;
    float acc[4][2];
#pragma unroll
    for (int q = 0; q < 4; q++) { acc[q][0] = 0.f; acc[q][1] = 0.f; }

    for (int kc = 0; kc < K; kc += 32) {
        __syncthreads();
#pragma unroll
        for (int q = 0; q < 4; q++) {
            int idx = tid + q * 256;
            int r = idx >> 3, c = (idx & 7) * 4;
            float4 w = *reinterpret_cast<const float4*>(W + (size_t)(j0 + r) * K + kc + c);
            Ws[r][c] = w.x; Ws[r][c + 1] = w.y; Ws[r][c + 2] = w.z; Ws[r][c + 3] = w.w;
        }
#pragma unroll
        for (int q = 0; q < 2; q++) {
            int e = tid + q * 256;
            int k = e >> 4, bb = e & 15;
            float xv;
            if (z == 0) xv = emb[(size_t)stok[bb] * E + kc + k];
            else        xv = lh[(size_t)(b0 + bb) * H + kc + k];
            Xs[k][bb] = xv;
        }
        __syncthreads();
#pragma unroll
        for (int k = 0; k < 32; k++) {
            float x0 = Xs[k][tb * 2], x1 = Xs[k][tb * 2 + 1];
#pragma unroll
            for (int q = 0; q < 4; q++) {
                float w = Ws[tj + q * 32][k];
                acc[q][0] += w * x0;
                acc[q][1] += w * x1;
            }
        }
    }
#pragma unroll
    for (int q = 0; q < 4; q++) {
        int j = j0 + tj + q * 32;
        Cdst[(size_t)(b0 + tb * 2) * J3H + j]     = acc[q][0];
        Cdst[(size_t)(b0 + tb * 2 + 1) * J3H + j] = acc[q][1];
    }
}

// ============================================================
// K2: GRU gates; zeros g_ectx, g_sumT, g_lhb (champion)
// ============================================================
__global__ void k_gates(const float* __restrict__ lh,
                        const float* __restrict__ b_ih,
                        const float* __restrict__ b_hh,
                        const float* __restrict__ w_h,
                        const float* __restrict__ w_d,
                        float* __restrict__ out) {
    int b = blockIdx.x >> 2;
    int i = ((blockIdx.x & 3) << 7) + threadIdx.x;
    if ((blockIdx.x & 3) == 0) {
        if (threadIdx.x == 0) g_sumT[b] = 0.f;
        g_lhb[(size_t)b * E + threadIdx.x] = 0.f;
    }
    float gx0 = g_gx[(size_t)b * J3H + i]         + b_ih[i];
    float gh0 = g_gh[(size_t)b * J3H + i]         + b_hh[i];
    float gx1 = g_gx[(size_t)b * J3H + H + i]     + b_ih[H + i];
    float gh1 = g_gh[(size_t)b * J3H + H + i]     + b_hh[H + i];
    float gx2 = g_gx[(size_t)b * J3H + 2 * H + i] + b_ih[2 * H + i];
    float gh2 = g_gh[(size_t)b * J3H + 2 * H + i] + b_hh[2 * H + i];
    float r = 1.f / (1.f + __expf(-(gx0 + gh0)));
    float z = 1.f / (1.f + __expf(-(gx1 + gh1)));
    float n = tanhf(gx2 + r * gh2);
    float hl = lh[(size_t)b * H + i];
    float h = (1.f - z) * n + z * hl;
    g_h[(size_t)b * H + i]   = h;
    g_hw[(size_t)b * H + i]  = h * w_h[i];
    g_hwd[(size_t)b * H + i] = h * w_d[i];
    g_ectx[(size_t)b * H + i] = 0.f;
    out[HH_OFF + (size_t)b * H + i] = h;
    out[DH_OFF + ((size_t)b * (T + 1) + T) * H + i] = h;
}

// ============================================================
// K3: att_scores — 2 s-rows per warp (champion)
// ============================================================
__global__ void k_attsc(const float* __restrict__ enc) {
    int b = blockIdx.y;
    int w = threadIdx.x >> 5, lane = threadIdx.x & 31;
    int s = blockIdx.x * 16 + w * 2;
    const float4* e0 = reinterpret_cast<const float4*>(enc + ((size_t)b * S + s) * H);
    const float4* e1 = reinterpret_cast<const float4*>(enc + ((size_t)b * S + s + 1) * H);
    const float4* h4 = reinterpret_cast<const float4*>(g_hw + (size_t)b * H);
    float acc0 = 0.f, acc1 = 0.f;
#pragma unroll
    for (int q = 0; q < 4; q++) {
        int idx = q * 32 + lane;
        float4 a = e0[idx];
        float4 c = e1[idx];
        float4 hv = h4[idx];
        acc0 += a.x * hv.x + a.y * hv.y + a.z * hv.z + a.w * hv.w;
        acc1 += c.x * hv.x + c.y * hv.y + c.z * hv.z + c.w * hv.w;
    }
    for (int o = 16; o; o >>= 1) {
        acc0 += __shfl_xor_sync(0xffffffffu, acc0, o);
        acc1 += __shfl_xor_sync(0xffffffffu, acc1, o);
    }
    if (!lane) {
        g_att_scores[b * S + s]     = acc0;
        g_att_scores[b * S + s + 1] = acc1;
    }
}

// ============================================================
// K4: temporal (champion)
// ============================================================
__global__ void k_temporal(const float* __restrict__ pa, float* __restrict__ out) {
    int b = blockIdx.y;
    int s = blockIdx.x * 200 + threadIdx.x;
    float tmp = 0.f;
    bool valid = (threadIdx.x < 200);
    if (valid) {
        float denom = 0.f;
        for (int t = 0; t < T; t++) {
            float v = pa[((size_t)b * T + t) * S + s];
            out[NPA_OFF + ((size_t)b * (T + 1) + t) * S + s] = v;
            denom += __expf(v);
        }
        float asc = g_att_scores[b * S + s];
        out[NPA_OFF + ((size_t)b * (T + 1) + T) * S + s] = asc;
        tmp = __expf(asc) / denom;
        g_tu[(size_t)b * S + s] = tmp;
    }
    float v = tmp;
    for (int o = 16; o; o >>= 1) v += __shfl_xor_sync(0xffffffffu, v, o);
    if ((threadIdx.x & 31) == 0 && v != 0.f) atomicAdd(&g_sumT[b], v);
}

// ============================================================
// K5: encoder_context + att_dist (champion)
// ============================================================
__global__ void k_ectx(const float* __restrict__ enc, float* __restrict__ out) {
    __shared__ float att[40];
    int sy = blockIdx.x, b = blockIdx.y;
    int s0 = sy * 40;
    int h = threadIdx.x;
    float rsum = __fdividef(1.f, g_sumT[b]);
    if (h < 40) {
        float a = g_tu[(size_t)b * S + s0 + h] * rsum;
        att[h] = a;
        out[AD_OFF + (size_t)b * S + s0 + h] = a;
    }
    __syncthreads();
    float a0 = 0, a1 = 0, a2 = 0, a3 = 0, a4 = 0, a5 = 0, a6 = 0, a7 = 0;
    const float* eb = enc + ((size_t)b * S + s0) * H + h;
#pragma unroll
    for (int s = 0; s < 40; s += 8) {
        a0 += att[s + 0] * eb[(size_t)(s + 0) * H];
        a1 += att[s + 1] * eb[(size_t)(s + 1) * H];
        a2 += att[s + 2] * eb[(size_t)(s + 2) * H];
        a3 += att[s + 3] * eb[(size_t)(s + 3) * H];
        a4 += att[s + 4] * eb[(size_t)(s + 4) * H];
        a5 += att[s + 5] * eb[(size_t)(s + 5) * H];
        a6 += att[s + 6] * eb[(size_t)(s + 6) * H];
        a7 += att[s + 7] * eb[(size_t)(s + 7) * H];
    }
    atomicAdd(&g_ectx[(size_t)b * H + h], ((a0 + a1) + (a2 + a3)) + ((a4 + a5) + (a6 + a7)));
}

// ============================================================
// K6: decoder attention + DH copy (champion)
// ============================================================
__global__ void k_dec(const float* __restrict__ pds, float* __restrict__ out) {
    extern __shared__ float sm[];
    float* pd = sm;
    float* sc = sm + T * H;
    float* at = sc + 64;
    int b = blockIdx.x, tid = threadIdx.x;
    for (int idx = tid; idx < T * H; idx += 512) {
        float v = pds[(size_t)b * T * H + idx];
        pd[idx] = v;
        int t = idx >> 9, hh = idx & 511;
        out[DH_OFF + ((size_t)b * (T + 1) + t) * H + hh] = v;
    }
    __syncthreads();
    int w = tid >> 5, lane = tid & 31;
    for (int t = w; t < T; t += 16) {
        float acc = 0.f;
#pragma unroll
        for (int q = 0; q < 16; q++)
            acc += g_hwd[(size_t)b * H + q * 32 + lane] * pd[t * H + q * 32 + lane];
        for (int o = 16; o; o >>= 1) acc += __shfl_xor_sync(0xffffffffu, acc, o);
        if (!lane) sc[t] = acc;
    }
    __syncthreads();
    if (tid < 32) {
        float s1 = (tid < T) ? sc[tid] : -1e30f;
        float s2 = (tid + 32 < T) ? sc[tid + 32] : -1e30f;
        float m = fmaxf(s1, s2);
        for (int o = 16; o; o >>= 1) m = fmaxf(m, __shfl_xor_sync(0xffffffffu, m, o));
        float e1 = (tid < T) ? __expf(s1 - m) : 0.f;
        float e2 = (tid + 32 < T) ? __expf(s2 - m) : 0.f;
        float sum = e1 + e2;
        for (int o = 16; o; o >>= 1) sum += __shfl_xor_sync(0xffffffffu, sum, o);
        if (tid < T) at[tid] = e1 / sum;
        if (tid + 32 < T) at[tid + 32] = e2 / sum;
    }
    __syncthreads();
    float acc = 0.f;
    for (int t = 0; t < T; t++) acc += at[t] * pd[t * H + tid];
    g_dctx[(size_t)b * H + tid] = acc;
}

// ============================================================
// K8: logits_h, split-K (champion)
// ============================================================
__global__ void k_outh(const float* __restrict__ Wo, const float* __restrict__ bo,
                       const float* __restrict__ ctrl) {
    __shared__ float Ws[8 * 128];
    __shared__ float Cs[32 * 129];
    int el = threadIdx.x >> 5, bl = threadIdx.x & 31;
    int e = blockIdx.x * 8 + el, bb = blockIdx.y * 32 + bl;
    int kbase = blockIdx.z * 768;
    float acc = 0.f;
    for (int kq = 0; kq < 768; kq += 128) {
        int kc = kbase + kq;
        __syncthreads();
        for (int idx = threadIdx.x; idx < 1024; idx += 256) {
            int ee = idx >> 7, k = idx & 127;
            Ws[idx] = Wo[(size_t)(blockIdx.x * 8 + ee) * CB + kc + k];
        }
        const float* src = (kc < 512) ? (g_h + kc)
                         : (kc < 1024) ? (g_ectx + kc - 512)
                                       : (g_dctx + kc - 1024);
        for (int idx = threadIdx.x; idx < 4096; idx += 256) {
            int b2 = idx >> 7, k = idx & 127;
            Cs[b2 * 129 + k] = src[(size_t)(blockIdx.y * 32 + b2) * H + k];
        }
        __syncthreads();
#pragma unroll 8
        for (int k = 0; k < 128; k++)
            acc += Ws[el * 128 + k] * Cs[bl * 129 + k];
    }
    if (blockIdx.z == 1)
        acc += Wo[(size_t)e * CB + 1536] * ctrl[bb] + bo[e];
    atomicAdd(&g_lhb[(size_t)bb * E + e], acc);
}

// ============================================================
// K9: p_gen; zeros g_sumexp (champion)
// ============================================================
__global__ void k_pgen(const float* __restrict__ gw, const float* __restrict__ gb,
                       const float* __restrict__ ctrl, float* __restrict__ out) {
    int b = blockIdx.x * 8 + (threadIdx.x >> 5);
    int lane = threadIdx.x & 31;
    float acc = 0.f;
    for (int k = lane; k < H; k += 32) {
        acc += g_h[(size_t)b * H + k]    * gw[k];
        acc += g_ectx[(size_t)b * H + k] * gw[H + k];
        acc += g_dctx[(size_t)b * H + k] * gw[2 * H + k];
    }
    if (!lane) acc += ctrl[b] * gw[1536];
    for (int o = 16; o; o >>= 1) acc += __shfl_xor_sync(0xffffffffu, acc, o);
    if (!lane) {
        out[PG_OFF + b] = 1.f / (1.f + __expf(-(acc + gb[0])));
        g_sumexp[b] = 0.f;
    }
}

// ============================================================
// K10: vocab GEMM — 64-row V tiles, 256 threads, 2 CTA/SM.
// grid (782). Writes exp into p_vocab output slot.
// ============================================================
__global__ void __launch_bounds__(256, 2)
k_outv_mma(const float* __restrict__ Wv, const float* __restrict__ bv,
           float* __restrict__ out) {
    extern __shared__ char smc[];
    __shared__ float s_bv[64];
    int tid = threadIdx.x;
    int vbase = blockIdx.x * 64;

    if (tid < 64) s_bv[tid] = (vbase + tid < V) ? bv[vbase + tid] : 0.f;

    // A (X) tile: 128 rows x 128 k -> 4096 float4, 16 iters
#pragma unroll
    for (int q = 0; q < 16; q++) {
        int idx = tid + q * 256;
        int r = idx >> 5;
        int c = (idx & 31) * 4;
        float4 x = *reinterpret_cast<const float4*>(g_lhb + (size_t)r * E + c);
        uint32_t h0, l0, h1, l1;
        split2(x.x, x.y, h0, l0);
        split2(x.z, x.w, h1, l1);
        size_t off = (size_t)(r * TSTR + c) * 2;
        *reinterpret_cast<uint2*>(smc + AHI_O + off) = make_uint2(h0, h1);
        *reinterpret_cast<uint2*>(smc + ALO_O + off) = make_uint2(l0, l1);
    }
    // B (W) tile: 64 rows x 128 k -> 2048 float4, 8 iters
#pragma unroll
    for (int q = 0; q < 8; q++) {
        int idx = tid + q * 256;
        int r = idx >> 5;
        int c = (idx & 31) * 4;
        float4 w = make_float4(0.f, 0.f, 0.f, 0.f);
        if (vbase + r < V) w = *reinterpret_cast<const float4*>(Wv + (size_t)(vbase + r) * E + c);
        uint32_t h0, l0, h1, l1;
        split2(w.x, w.y, h0, l0);
        split2(w.z, w.w, h1, l1);
        size_t off = (size_t)(r * TSTR + c) * 2;
        *reinterpret_cast<uint2*>(smc + BHI_O + off) = make_uint2(h0, h1);
        *reinterpret_cast<uint2*>(smc + BLO_O + off) = make_uint2(l0, l1);
    }
    __syncthreads();

    int wid = tid >> 5, lane = tid & 31;
    int wm = wid >> 1, wn = wid & 1;     // 4 m-warps x 2 n-warps
    int g = lane >> 2, t = lane & 3;

    float acc[2][4][4];
#pragma unroll
    for (int mi = 0; mi < 2; mi++)
#pragma unroll
        for (int ni = 0; ni < 4; ni++)
#pragma unroll
            for (int r = 0; r < 4; r++) acc[mi][ni][r] = 0.f;

    mma_chunk(smc, wm, wn, g, t, acc);
    __syncthreads();

    // epilogue: bias + exp into stage [128][TST2]
    float* stage = reinterpret_cast<float*>(smc);
#pragma unroll
    for (int mi = 0; mi < 2; mi++) {
        int r0 = wm * 32 + mi * 16 + g;
#pragma unroll
        for (int ni = 0; ni < 4; ni++) {
            int n0 = wn * 32 + ni * 8 + 2 * t;
            bool v0 = (vbase + n0 < V), v1 = (vbase + n0 + 1 < V);
            float e00 = v0 ? __expf(acc[mi][ni][0] + s_bv[n0])     : 0.f;
            float e01 = v1 ? __expf(acc[mi][ni][1] + s_bv[n0 + 1]) : 0.f;
            float e10 = v0 ? __expf(acc[mi][ni][2] + s_bv[n0])     : 0.f;
            float e11 = v1 ? __expf(acc[mi][ni][3] + s_bv[n0 + 1]) : 0.f;
            stage[r0 * TST2 + n0]           = e00;
            stage[r0 * TST2 + n0 + 1]       = e01;
            stage[(r0 + 8) * TST2 + n0]     = e10;
            stage[(r0 + 8) * TST2 + n0 + 1] = e11;
        }
    }
    __syncthreads();

    // row sums: 256 threads = 128 rows x 2 halves of 32 cols
    {
        int row = tid >> 1, half = tid & 1;
        float lsum = 0.f;
#pragma unroll
        for (int c = half * 32; c < half * 32 + 32; c++) lsum += stage[row * TST2 + c];
        atomicAdd(&g_sumexp[row], lsum);
    }
    // store exp into p_vocab slot: 128 x 64 elems
    for (int idx = tid; idx < 128 * 64; idx += 256) {
        int b = idx >> 6, c = idx & 63;
        if (vbase + c < V)
            out[PV_OFF + (size_t)b * V + vbase + c] = stage[b * TST2 + c];
    }
}

// ============================================================
// K11: normalize p_vocab in place + p_final (champion)
// ============================================================
__global__ void k_pfinal(float* __restrict__ out) {
    int b = blockIdx.y;
    int v = (blockIdx.x * 256 + threadIdx.x) * 4;
    if (v >= VP) return;
    float pg = out[PG_OFF + b];
    if (v < V) {
        float4 u = *reinterpret_cast<const float4*>(out + PV_OFF + (size_t)b * V + v);
        float inv = __fdividef(1.f, g_sumexp[b]);
        float4 p = make_float4(u.x * inv, u.y * inv, u.z * inv, u.w * inv);
        *reinterpret_cast<float4*>(out + PV_OFF + (size_t)b * V + v) = p;
        *reinterpret_cast<float4*>(out + PF_OFF + (size_t)b * VP + v) =
            make_float4(p.x * pg, p.y * pg, p.z * pg, p.w * pg);
    } else {
        *reinterpret_cast<float4*>(out + PF_OFF + (size_t)b * VP + v) =
            make_float4(0.f, 0.f, 0.f, 0.f);
    }
}

// ============================================================
// K12: pointer scatter (champion)
// ============================================================
__global__ void k_scatter(const int* __restrict__ fiv, float* __restrict__ out) {
    int b = blockIdx.x, s = threadIdx.x;
    if (s < S) {
        float pg = out[PG_OFF + b];
        float val = (1.f - pg) * out[AD_OFF + (size_t)b * S + s];
        int idx = fiv[(size_t)b * S + s];
        atomicAdd(&out[PF_OFF + (size_t)b * VP + idx], val);
    }
}

// ============================================================
// launch — champion graph
// ============================================================
extern "C" void kernel_launch(void* const* d_in, const int* in_sizes, int n_in,
                              void* d_out, int out_size) {
    const int*   tok    = (const int*)  d_in[0];
    const float* pds    = (const float*)d_in[1];
    const float* lh     = (const float*)d_in[2];
    const float* enc    = (const float*)d_in[3];
    const int*   fiv    = (const int*)  d_in[4];
    const float* pa     = (const float*)d_in[5];
    const float* ctrl   = (const float*)d_in[6];
    const float* emb    = (const float*)d_in[7];
    const float* W_ih   = (const float*)d_in[8];
    const float* W_hh   = (const float*)d_in[9];
    const float* b_ih   = (const float*)d_in[10];
    const float* b_hh   = (const float*)d_in[11];
    const float* w_h    = (const float*)d_in[12];
    const float* w_d    = (const float*)d_in[13];
    const float* gen_W  = (const float*)d_in[14];
    const float* gen_b  = (const float*)d_in[15];
    const float* outh_W = (const float*)d_in[16];
    const float* outh_b = (const float*)d_in[17];
    const float* outv_W = (const float*)d_in[18];
    const float* outv_b = (const float*)d_in[19];
    float* out = (float*)d_out;

    const int DEC_SMEM = (T * H + 128) * sizeof(float);
    cudaFuncSetAttribute(k_dec, cudaFuncAttributeMaxDynamicSharedMemorySize, DEC_SMEM);
    cudaFuncSetAttribute(k_outv_mma, cudaFuncAttributeMaxDynamicSharedMemorySize, MMA_DSMEM);

    cudaStream_t s1;
    cudaStreamCreateWithFlags(&s1, cudaStreamNonBlocking);
    cudaEvent_t evGates, evDec, evEctx, evPgen;
    cudaEventCreateWithFlags(&evGates, cudaEventDisableTiming);
    cudaEventCreateWithFlags(&evDec,   cudaEventDisableTiming);
    cudaEventCreateWithFlags(&evEctx,  cudaEventDisableTiming);
    cudaEventCreateWithFlags(&evPgen,  cudaEventDisableTiming);

    // main stream: GRU
    k_grugemm<<<dim3(J3H / 128, B / 16, 2), 256>>>(W_ih, W_hh, tok, emb, lh);
    k_gates<<<4 * B, 128>>>(lh, b_ih, b_hh, w_h, w_d, out);
    cudaEventRecord(evGates, 0);

    // side stream: decoder attention (fork AFTER chain start)
    cudaStreamWaitEvent(s1, evGates, 0);
    k_dec<<<B, 512, DEC_SMEM, s1>>>(pds, out);
    cudaEventRecord(evDec, s1);

    // main stream: encoder attention chain
    k_attsc<<<dim3(S / 16, B), 256>>>(enc);
    k_temporal<<<dim3(2, B), 256>>>(pa, out);
    k_ectx<<<dim3(10, B), 512>>>(enc, out);
    cudaEventRecord(evEctx, 0);

    // side stream: p_gen (needs ectx + dctx); zeros g_sumexp
    cudaStreamWaitEvent(s1, evEctx, 0);
    k_pgen<<<16, 256, 0, s1>>>(gen_W, gen_b, ctrl, out);
    cudaEventRecord(evPgen, s1);

    // main stream: output head (split-K), vocab GEMM, finals
    cudaStreamWaitEvent(0, evDec, 0);
    k_outh<<<dim3(16, 4, 2), 256>>>(outh_W, outh_b, ctrl);
    cudaStreamWaitEvent(0, evPgen, 0);   // sumexp zeroed before outv atomics
    k_outv_mma<<<(V + 63) / 64, 256, MMA_DSMEM>>>(outv_W, outv_b, out);
    k_pfinal<<<dim3((VP / 4 + 255) / 256, B), 256>>>(out);
    k_scatter<<<B, 512>>>(fiv, out);

    cudaEventDestroy(evGates);
    cudaEventDestroy(evDec);
    cudaEventDestroy(evEctx);
    cudaEventDestroy(evPgen);
    cudaStreamDestroy(s1);
}

// round 16
// speedup vs baseline: 1.4745x; 1.0044x over previous
#include <cuda_runtime.h>
#include <cuda_bf16.h>
#include <math.h>
#include <stdint.h>

// Problem constants
#define B    128
#define S    400
#define T    50
#define H    512
#define E    128
#define V    50000
#define PADN 1000
#define J3H  1536
#define CB   1537
#define VP   51000

// ---- output layout (flattened tuple, float32) ----
#define PF_OFF  ((size_t)0)
#define PG_OFF  (PF_OFF + (size_t)B*VP)
#define PV_OFF  (PG_OFF + (size_t)B)
#define AD_OFF  (PV_OFF + (size_t)B*V)
#define DH_OFF  (AD_OFF + (size_t)B*S)
#define HH_OFF  (DH_OFF + (size_t)B*(T+1)*H)
#define NPA_OFF (HH_OFF + (size_t)B*H)

// ---- device scratch ----
__device__ __align__(16) float g_gx[B * J3H];
__device__ __align__(16) float g_gh[B * J3H];
__device__ __align__(16) float g_h[B * H];
__device__ __align__(16) float g_hw[B * H];
__device__ __align__(16) float g_hwd[B * H];
__device__ __align__(16) float g_att_scores[B * S];
__device__ __align__(16) float g_tu[B * S];
__device__ __align__(16) float g_sumT[B];
__device__ __align__(16) float g_ectx[B * H];
__device__ __align__(16) float g_dctx[B * H];
__device__ __align__(16) float g_lhb[B * E];    // logits_h (split-K accumulated)
__device__ __align__(16) float g_sumexp[B];

// ---- mma machinery (bf16 3-term split), conflict-free TSTR=136 ----
// 64-row B tiles for 2 CTAs/SM occupancy.
#define TSTR  136
#define ATILE (128 * TSTR * 2)          // A: 128 rows
#define BTILE (64 * TSTR * 2)           // B: 64 rows
#define AHI_O 0
#define ALO_O (ATILE)
#define BHI_O (2 * ATILE)
#define BLO_O (2 * ATILE + BTILE)
#define MMA_DSMEM (2 * ATILE + 2 * BTILE)   // 104448 B
#define TST2  68                         // epilogue stage stride (64+4)

__device__ __forceinline__ void split2(float a, float b, uint32_t& hv, uint32_t& lv) {
    __nv_bfloat162 hi = __float22bfloat162_rn(make_float2(a, b));
    float ra = a - __bfloat162float(hi.x);
    float rb = b - __bfloat162float(hi.y);
    __nv_bfloat162 lo = __float22bfloat162_rn(make_float2(ra, rb));
    hv = *reinterpret_cast<uint32_t*>(&hi);
    lv = *reinterpret_cast<uint32_t*>(&lo);
}
__device__ __forceinline__ void mma16816(float* c, const uint32_t* a, const uint32_t* b) {
    asm volatile(
        "mma.sync.aligned.m16n8k16.row.col.f32.bf16.bf16.f32 "
        "{%0,%1,%2,%3}, {%4,%5,%6,%7}, {%8,%9}, {%0,%1,%2,%3};"
        : "+f"(c[0]), "+f"(c[1]), "+f"(c[2]), "+f"(c[3])
        : "r"(a[0]), "r"(a[1]), "r"(a[2]), "r"(a[3]), "r"(b[0]), "r"(b[1]));
}
__device__ __forceinline__ void mma_chunk(char* smc, int wm, int wn, int g, int t,
                                          float acc[2][4][4]) {
#pragma unroll
    for (int term = 0; term < 3; term++) {
        int aoff = (term == 2) ? ALO_O : AHI_O;
        int boff = (term == 1) ? BLO_O : BHI_O;
#pragma unroll
        for (int ks = 0; ks < 8; ks++) {
            int kb = ks * 16;
            uint32_t af[2][4], bf[4][2];
#pragma unroll
            for (int mi = 0; mi < 2; mi++) {
                int row = wm * 32 + mi * 16 + g;
                size_t o = (size_t)aoff + (size_t)(row * TSTR + kb + 2 * t) * 2;
                af[mi][0] = *reinterpret_cast<const uint32_t*>(smc + o);
                af[mi][1] = *reinterpret_cast<const uint32_t*>(smc + o + 8 * TSTR * 2);
                af[mi][2] = *reinterpret_cast<const uint32_t*>(smc + o + 16);
                af[mi][3] = *reinterpret_cast<const uint32_t*>(smc + o + 8 * TSTR * 2 + 16);
            }
#pragma unroll
            for (int ni = 0; ni < 4; ni++) {
                int row = wn * 32 + ni * 8 + g;
                size_t o = (size_t)boff + (size_t)(row * TSTR + kb + 2 * t) * 2;
                bf[ni][0] = *reinterpret_cast<const uint32_t*>(smc + o);
                bf[ni][1] = *reinterpret_cast<const uint32_t*>(smc + o + 16);
            }
#pragma unroll
            for (int mi = 0; mi < 2; mi++)
#pragma unroll
                for (int ni = 0; ni < 4; ni++)
                    mma16816(acc[mi][ni], af[mi], bf[ni]);
        }
    }
}

// ============================================================
// K1: fused GRU GEMMs (champion)
// ============================================================
__global__ void __launch_bounds__(256) k_grugemm(const float* __restrict__ Wih,
                                                 const float* __restrict__ Whh,
                                                 const int* __restrict__ tok,
                                                 const float* __restrict__ emb,
                                                 const float* __restrict__ lh) {
    int z = blockIdx.z;
    const float* W = z ? Whh : Wih;
    float* Cdst    = z ? g_gh : g_gx;
    int K = z ? H : E;

    __shared__ float Ws[128][33];
    __shared__ float Xs[32][17];
    __shared__ int stok[16];
    int tid = threadIdx.x;
    int j0 = blockIdx.x * 128, b0 = blockIdx.y * 16;
    if (tid < 16) stok[tid] = tok[b0 + tid];
    int tj = tid & 31, tb = tid >> 5;
    float acc[4][2];
#pragma unroll
    for (int q = 0; q < 4; q++) { acc[q][0] = 0.f; acc[q][1] = 0.f; }

    for (int kc = 0; kc < K; kc += 32) {
        __syncthreads();
#pragma unroll
        for (int q = 0; q < 4; q++) {
            int idx = tid + q * 256;
            int r = idx >> 3, c = (idx & 7) * 4;
            float4 w = *reinterpret_cast<const float4*>(W + (size_t)(j0 + r) * K + kc + c);
            Ws[r][c] = w.x; Ws[r][c + 1] = w.y; Ws[r][c + 2] = w.z; Ws[r][c + 3] = w.w;
        }
#pragma unroll
        for (int q = 0; q < 2; q++) {
            int e = tid + q * 256;
            int k = e >> 4, bb = e & 15;
            float xv;
            if (z == 0) xv = emb[(size_t)stok[bb] * E + kc + k];
            else        xv = lh[(size_t)(b0 + bb) * H + kc + k];
            Xs[k][bb] = xv;
        }
        __syncthreads();
#pragma unroll
        for (int k = 0; k < 32; k++) {
            float x0 = Xs[k][tb * 2], x1 = Xs[k][tb * 2 + 1];
#pragma unroll
            for (int q = 0; q < 4; q++) {
                float w = Ws[tj + q * 32][k];
                acc[q][0] += w * x0;
                acc[q][1] += w * x1;
            }
        }
    }
#pragma unroll
    for (int q = 0; q < 4; q++) {
        int j = j0 + tj + q * 32;
        Cdst[(size_t)(b0 + tb * 2) * J3H + j]     = acc[q][0];
        Cdst[(size_t)(b0 + tb * 2 + 1) * J3H + j] = acc[q][1];
    }
}

// ============================================================
// K2: GRU gates; zeros g_ectx, g_sumT, g_lhb (champion)
// ============================================================
__global__ void k_gates(const float* __restrict__ lh,
                        const float* __restrict__ b_ih,
                        const float* __restrict__ b_hh,
                        const float* __restrict__ w_h,
                        const float* __restrict__ w_d,
                        float* __restrict__ out) {
    int b = blockIdx.x >> 2;
    int i = ((blockIdx.x & 3) << 7) + threadIdx.x;
    if ((blockIdx.x & 3) == 0) {
        if (threadIdx.x == 0) g_sumT[b] = 0.f;
        g_lhb[(size_t)b * E + threadIdx.x] = 0.f;
    }
    float gx0 = g_gx[(size_t)b * J3H + i]         + b_ih[i];
    float gh0 = g_gh[(size_t)b * J3H + i]         + b_hh[i];
    float gx1 = g_gx[(size_t)b * J3H + H + i]     + b_ih[H + i];
    float gh1 = g_gh[(size_t)b * J3H + H + i]     + b_hh[H + i];
    float gx2 = g_gx[(size_t)b * J3H + 2 * H + i] + b_ih[2 * H + i];
    float gh2 = g_gh[(size_t)b * J3H + 2 * H + i] + b_hh[2 * H + i];
    float r = 1.f / (1.f + __expf(-(gx0 + gh0)));
    float z = 1.f / (1.f + __expf(-(gx1 + gh1)));
    float n = tanhf(gx2 + r * gh2);
    float hl = lh[(size_t)b * H + i];
    float h = (1.f - z) * n + z * hl;
    g_h[(size_t)b * H + i]   = h;
    g_hw[(size_t)b * H + i]  = h * w_h[i];
    g_hwd[(size_t)b * H + i] = h * w_d[i];
    g_ectx[(size_t)b * H + i] = 0.f;
    out[HH_OFF + (size_t)b * H + i] = h;
    out[DH_OFF + ((size_t)b * (T + 1) + T) * H + i] = h;
}

// ============================================================
// K3: att_scores — 2 s-rows per warp (champion)
// ============================================================
__global__ void k_attsc(const float* __restrict__ enc) {
    int b = blockIdx.y;
    int w = threadIdx.x >> 5, lane = threadIdx.x & 31;
    int s = blockIdx.x * 16 + w * 2;
    const float4* e0 = reinterpret_cast<const float4*>(enc + ((size_t)b * S + s) * H);
    const float4* e1 = reinterpret_cast<const float4*>(enc + ((size_t)b * S + s + 1) * H);
    const float4* h4 = reinterpret_cast<const float4*>(g_hw + (size_t)b * H);
    float acc0 = 0.f, acc1 = 0.f;
#pragma unroll
    for (int q = 0; q < 4; q++) {
        int idx = q * 32 + lane;
        float4 a = e0[idx];
        float4 c = e1[idx];
        float4 hv = h4[idx];
        acc0 += a.x * hv.x + a.y * hv.y + a.z * hv.z + a.w * hv.w;
        acc1 += c.x * hv.x + c.y * hv.y + c.z * hv.z + c.w * hv.w;
    }
    for (int o = 16; o; o >>= 1) {
        acc0 += __shfl_xor_sync(0xffffffffu, acc0, o);
        acc1 += __shfl_xor_sync(0xffffffffu, acc1, o);
    }
    if (!lane) {
        g_att_scores[b * S + s]     = acc0;
        g_att_scores[b * S + s + 1] = acc1;
    }
}

// ============================================================
// K4: temporal (champion)
// ============================================================
__global__ void k_temporal(const float* __restrict__ pa, float* __restrict__ out) {
    int b = blockIdx.y;
    int s = blockIdx.x * 200 + threadIdx.x;
    float tmp = 0.f;
    bool valid = (threadIdx.x < 200);
    if (valid) {
        float denom = 0.f;
        for (int t = 0; t < T; t++) {
            float v = pa[((size_t)b * T + t) * S + s];
            out[NPA_OFF + ((size_t)b * (T + 1) + t) * S + s] = v;
            denom += __expf(v);
        }
        float asc = g_att_scores[b * S + s];
        out[NPA_OFF + ((size_t)b * (T + 1) + T) * S + s] = asc;
        tmp = __expf(asc) / denom;
        g_tu[(size_t)b * S + s] = tmp;
    }
    float v = tmp;
    for (int o = 16; o; o >>= 1) v += __shfl_xor_sync(0xffffffffu, v, o);
    if ((threadIdx.x & 31) == 0 && v != 0.f) atomicAdd(&g_sumT[b], v);
}

// ============================================================
// K5: encoder_context + att_dist (champion)
// ============================================================
__global__ void k_ectx(const float* __restrict__ enc, float* __restrict__ out) {
    __shared__ float att[40];
    int sy = blockIdx.x, b = blockIdx.y;
    int s0 = sy * 40;
    int h = threadIdx.x;
    float rsum = __fdividef(1.f, g_sumT[b]);
    if (h < 40) {
        float a = g_tu[(size_t)b * S + s0 + h] * rsum;
        att[h] = a;
        out[AD_OFF + (size_t)b * S + s0 + h] = a;
    }
    __syncthreads();
    float a0 = 0, a1 = 0, a2 = 0, a3 = 0, a4 = 0, a5 = 0, a6 = 0, a7 = 0;
    const float* eb = enc + ((size_t)b * S + s0) * H + h;
#pragma unroll
    for (int s = 0; s < 40; s += 8) {
        a0 += att[s + 0] * eb[(size_t)(s + 0) * H];
        a1 += att[s + 1] * eb[(size_t)(s + 1) * H];
        a2 += att[s + 2] * eb[(size_t)(s + 2) * H];
        a3 += att[s + 3] * eb[(size_t)(s + 3) * H];
        a4 += att[s + 4] * eb[(size_t)(s + 4) * H];
        a5 += att[s + 5] * eb[(size_t)(s + 5) * H];
        a6 += att[s + 6] * eb[(size_t)(s + 6) * H];
        a7 += att[s + 7] * eb[(size_t)(s + 7) * H];
    }
    atomicAdd(&g_ectx[(size_t)b * H + h], ((a0 + a1) + (a2 + a3)) + ((a4 + a5) + (a6 + a7)));
}

// ============================================================
// K6: decoder attention + DH copy (champion)
// ============================================================
__global__ void k_dec(const float* __restrict__ pds, float* __restrict__ out) {
    extern __shared__ float sm[];
    float* pd = sm;
    float* sc = sm + T * H;
    float* at = sc + 64;
    int b = blockIdx.x, tid = threadIdx.x;
    for (int idx = tid; idx < T * H; idx += 512) {
        float v = pds[(size_t)b * T * H + idx];
        pd[idx] = v;
        int t = idx >> 9, hh = idx & 511;
        out[DH_OFF + ((size_t)b * (T + 1) + t) * H + hh] = v;
    }
    __syncthreads();
    int w = tid >> 5, lane = tid & 31;
    for (int t = w; t < T; t += 16) {
        float acc = 0.f;
#pragma unroll
        for (int q = 0; q < 16; q++)
            acc += g_hwd[(size_t)b * H + q * 32 + lane] * pd[t * H + q * 32 + lane];
        for (int o = 16; o; o >>= 1) acc += __shfl_xor_sync(0xffffffffu, acc, o);
        if (!lane) sc[t] = acc;
    }
    __syncthreads();
    if (tid < 32) {
        float s1 = (tid < T) ? sc[tid] : -1e30f;
        float s2 = (tid + 32 < T) ? sc[tid + 32] : -1e30f;
        float m = fmaxf(s1, s2);
        for (int o = 16; o; o >>= 1) m = fmaxf(m, __shfl_xor_sync(0xffffffffu, m, o));
        float e1 = (tid < T) ? __expf(s1 - m) : 0.f;
        float e2 = (tid + 32 < T) ? __expf(s2 - m) : 0.f;
        float sum = e1 + e2;
        for (int o = 16; o; o >>= 1) sum += __shfl_xor_sync(0xffffffffu, sum, o);
        if (tid < T) at[tid] = e1 / sum;
        if (tid + 32 < T) at[tid + 32] = e2 / sum;
    }
    __syncthreads();
    float acc = 0.f;
    for (int t = 0; t < T; t++) acc += at[t] * pd[t * H + tid];
    g_dctx[(size_t)b * H + tid] = acc;
}

// ============================================================
// K8: logits_h, split-K (champion)
// ============================================================
__global__ void k_outh(const float* __restrict__ Wo, const float* __restrict__ bo,
                       const float* __restrict__ ctrl) {
    __shared__ float Ws[8 * 128];
    __shared__ float Cs[32 * 129];
    int el = threadIdx.x >> 5, bl = threadIdx.x & 31;
    int e = blockIdx.x * 8 + el, bb = blockIdx.y * 32 + bl;
    int kbase = blockIdx.z * 768;
    float acc = 0.f;
    for (int kq = 0; kq < 768; kq += 128) {
        int kc = kbase + kq;
        __syncthreads();
        for (int idx = threadIdx.x; idx < 1024; idx += 256) {
            int ee = idx >> 7, k = idx & 127;
            Ws[idx] = Wo[(size_t)(blockIdx.x * 8 + ee) * CB + kc + k];
        }
        const float* src = (kc < 512) ? (g_h + kc)
                         : (kc < 1024) ? (g_ectx + kc - 512)
                                       : (g_dctx + kc - 1024);
        for (int idx = threadIdx.x; idx < 4096; idx += 256) {
            int b2 = idx >> 7, k = idx & 127;
            Cs[b2 * 129 + k] = src[(size_t)(blockIdx.y * 32 + b2) * H + k];
        }
        __syncthreads();
#pragma unroll 8
        for (int k = 0; k < 128; k++)
            acc += Ws[el * 128 + k] * Cs[bl * 129 + k];
    }
    if (blockIdx.z == 1)
        acc += Wo[(size_t)e * CB + 1536] * ctrl[bb] + bo[e];
    atomicAdd(&g_lhb[(size_t)bb * E + e], acc);
}

// ============================================================
// K9: p_gen; zeros g_sumexp (champion)
// ============================================================
__global__ void k_pgen(const float* __restrict__ gw, const float* __restrict__ gb,
                       const float* __restrict__ ctrl, float* __restrict__ out) {
    int b = blockIdx.x * 8 + (threadIdx.x >> 5);
    int lane = threadIdx.x & 31;
    float acc = 0.f;
    for (int k = lane; k < H; k += 32) {
        acc += g_h[(size_t)b * H + k]    * gw[k];
        acc += g_ectx[(size_t)b * H + k] * gw[H + k];
        acc += g_dctx[(size_t)b * H + k] * gw[2 * H + k];
    }
    if (!lane) acc += ctrl[b] * gw[1536];
    for (int o = 16; o; o >>= 1) acc += __shfl_xor_sync(0xffffffffu, acc, o);
    if (!lane) {
        out[PG_OFF + b] = 1.f / (1.f + __expf(-(acc + gb[0])));
        g_sumexp[b] = 0.f;
    }
}

// ============================================================
// K10: vocab GEMM — 64-row V tiles, 256 threads, 2 CTA/SM.
// grid (782). Writes exp into p_vocab output slot.
// ============================================================
__global__ void __launch_bounds__(256, 2)
k_outv_mma(const float* __restrict__ Wv, const float* __restrict__ bv,
           float* __restrict__ out) {
    extern __shared__ char smc[];
    __shared__ float s_bv[64];
    int tid = threadIdx.x;
    int vbase = blockIdx.x * 64;

    if (tid < 64) s_bv[tid] = (vbase + tid < V) ? bv[vbase + tid] : 0.f;

    // A (X) tile: 128 rows x 128 k -> 4096 float4, 16 iters
#pragma unroll
    for (int q = 0; q < 16; q++) {
        int idx = tid + q * 256;
        int r = idx >> 5;
        int c = (idx & 31) * 4;
        float4 x = *reinterpret_cast<const float4*>(g_lhb + (size_t)r * E + c);
        uint32_t h0, l0, h1, l1;
        split2(x.x, x.y, h0, l0);
        split2(x.z, x.w, h1, l1);
        size_t off = (size_t)(r * TSTR + c) * 2;
        *reinterpret_cast<uint2*>(smc + AHI_O + off) = make_uint2(h0, h1);
        *reinterpret_cast<uint2*>(smc + ALO_O + off) = make_uint2(l0, l1);
    }
    // B (W) tile: 64 rows x 128 k -> 2048 float4, 8 iters
#pragma unroll
    for (int q = 0; q < 8; q++) {
        int idx = tid + q * 256;
        int r = idx >> 5;
        int c = (idx & 31) * 4;
        float4 w = make_float4(0.f, 0.f, 0.f, 0.f);
        if (vbase + r < V) w = *reinterpret_cast<const float4*>(Wv + (size_t)(vbase + r) * E + c);
        uint32_t h0, l0, h1, l1;
        split2(w.x, w.y, h0, l0);
        split2(w.z, w.w, h1, l1);
        size_t off = (size_t)(r * TSTR + c) * 2;
        *reinterpret_cast<uint2*>(smc + BHI_O + off) = make_uint2(h0, h1);
        *reinterpret_cast<uint2*>(smc + BLO_O + off) = make_uint2(l0, l1);
    }
    __syncthreads();

    int wid = tid >> 5, lane = tid & 31;
    int wm = wid >> 1, wn = wid & 1;     // 4 m-warps x 2 n-warps
    int g = lane >> 2, t = lane & 3;

    float acc[2][4][4];
#pragma unroll
    for (int mi = 0; mi < 2; mi++)
#pragma unroll
        for (int ni = 0; ni < 4; ni++)
#pragma unroll
            for (int r = 0; r < 4; r++) acc[mi][ni][r] = 0.f;

    mma_chunk(smc, wm, wn, g, t, acc);
    __syncthreads();

    // epilogue: bias + exp into stage [128][TST2]
    float* stage = reinterpret_cast<float*>(smc);
#pragma unroll
    for (int mi = 0; mi < 2; mi++) {
        int r0 = wm * 32 + mi * 16 + g;
#pragma unroll
        for (int ni = 0; ni < 4; ni++) {
            int n0 = wn * 32 + ni * 8 + 2 * t;
            bool v0 = (vbase + n0 < V), v1 = (vbase + n0 + 1 < V);
            float e00 = v0 ? __expf(acc[mi][ni][0] + s_bv[n0])     : 0.f;
            float e01 = v1 ? __expf(acc[mi][ni][1] + s_bv[n0 + 1]) : 0.f;
            float e10 = v0 ? __expf(acc[mi][ni][2] + s_bv[n0])     : 0.f;
            float e11 = v1 ? __expf(acc[mi][ni][3] + s_bv[n0 + 1]) : 0.f;
            stage[r0 * TST2 + n0]           = e00;
            stage[r0 * TST2 + n0 + 1]       = e01;
            stage[(r0 + 8) * TST2 + n0]     = e10;
            stage[(r0 + 8) * TST2 + n0 + 1] = e11;
        }
    }
    __syncthreads();

    // row sums: 256 threads = 128 rows x 2 halves of 32 cols
    {
        int row = tid >> 1, half = tid & 1;
        float lsum = 0.f;
#pragma unroll
        for (int c = half * 32; c < half * 32 + 32; c++) lsum += stage[row * TST2 + c];
        atomicAdd(&g_sumexp[row], lsum);
    }
    // store exp into p_vocab slot: 128 x 64 elems
    for (int idx = tid; idx < 128 * 64; idx += 256) {
        int b = idx >> 6, c = idx & 63;
        if (vbase + c < V)
            out[PV_OFF + (size_t)b * V + vbase + c] = stage[b * TST2 + c];
    }
}

// ============================================================
// K11: normalize p_vocab in place + p_final (champion)
// ============================================================
__global__ void k_pfinal(float* __restrict__ out) {
    int b = blockIdx.y;
    int v = (blockIdx.x * 256 + threadIdx.x) * 4;
    if (v >= VP) return;
    float pg = out[PG_OFF + b];
    if (v < V) {
        float4 u = *reinterpret_cast<const float4*>(out + PV_OFF + (size_t)b * V + v);
        float inv = __fdividef(1.f, g_sumexp[b]);
        float4 p = make_float4(u.x * inv, u.y * inv, u.z * inv, u.w * inv);
        *reinterpret_cast<float4*>(out + PV_OFF + (size_t)b * V + v) = p;
        *reinterpret_cast<float4*>(out + PF_OFF + (size_t)b * VP + v) =
            make_float4(p.x * pg, p.y * pg, p.z * pg, p.w * pg);
    } else {
        *reinterpret_cast<float4*>(out + PF_OFF + (size_t)b * VP + v) =
            make_float4(0.f, 0.f, 0.f, 0.f);
    }
}

// ============================================================
// K12: pointer scatter (champion)
// ============================================================
__global__ void k_scatter(const int* __restrict__ fiv, float* __restrict__ out) {
    int b = blockIdx.x, s = threadIdx.x;
    if (s < S) {
        float pg = out[PG_OFF + b];
        float val = (1.f - pg) * out[AD_OFF + (size_t)b * S + s];
        int idx = fiv[(size_t)b * S + s];
        atomicAdd(&out[PF_OFF + (size_t)b * VP + idx], val);
    }
}

// ============================================================
// launch — champion graph
// ============================================================
extern "C" void kernel_launch(void* const* d_in, const int* in_sizes, int n_in,
                              void* d_out, int out_size) {
    const int*   tok    = (const int*)  d_in[0];
    const float* pds    = (const float*)d_in[1];
    const float* lh     = (const float*)d_in[2];
    const float* enc    = (const float*)d_in[3];
    const int*   fiv    = (const int*)  d_in[4];
    const float* pa     = (const float*)d_in[5];
    const float* ctrl   = (const float*)d_in[6];
    const float* emb    = (const float*)d_in[7];
    const float* W_ih   = (const float*)d_in[8];
    const float* W_hh   = (const float*)d_in[9];
    const float* b_ih   = (const float*)d_in[10];
    const float* b_hh   = (const float*)d_in[11];
    const float* w_h    = (const float*)d_in[12];
    const float* w_d    = (const float*)d_in[13];
    const float* gen_W  = (const float*)d_in[14];
    const float* gen_b  = (const float*)d_in[15];
    const float* outh_W = (const float*)d_in[16];
    const float* outh_b = (const float*)d_in[17];
    const float* outv_W = (const float*)d_in[18];
    const float* outv_b = (const float*)d_in[19];
    float* out = (float*)d_out;

    const int DEC_SMEM = (T * H + 128) * sizeof(float);
    cudaFuncSetAttribute(k_dec, cudaFuncAttributeMaxDynamicSharedMemorySize, DEC_SMEM);
    cudaFuncSetAttribute(k_outv_mma, cudaFuncAttributeMaxDynamicSharedMemorySize, MMA_DSMEM);

    cudaStream_t s1;
    cudaStreamCreateWithFlags(&s1, cudaStreamNonBlocking);
    cudaEvent_t evGates, evDec, evEctx, evPgen;
    cudaEventCreateWithFlags(&evGates, cudaEventDisableTiming);
    cudaEventCreateWithFlags(&evDec,   cudaEventDisableTiming);
    cudaEventCreateWithFlags(&evEctx,  cudaEventDisableTiming);
    cudaEventCreateWithFlags(&evPgen,  cudaEventDisableTiming);

    // main stream: GRU
    k_grugemm<<<dim3(J3H / 128, B / 16, 2), 256>>>(W_ih, W_hh, tok, emb, lh);
    k_gates<<<4 * B, 128>>>(lh, b_ih, b_hh, w_h, w_d, out);
    cudaEventRecord(evGates, 0);

    // side stream: decoder attention (fork AFTER chain start)
    cudaStreamWaitEvent(s1, evGates, 0);
    k_dec<<<B, 512, DEC_SMEM, s1>>>(pds, out);
    cudaEventRecord(evDec, s1);

    // main stream: encoder attention chain
    k_attsc<<<dim3(S / 16, B), 256>>>(enc);
    k_temporal<<<dim3(2, B), 256>>>(pa, out);
    k_ectx<<<dim3(10, B), 512>>>(enc, out);
    cudaEventRecord(evEctx, 0);

    // side stream: p_gen (needs ectx + dctx); zeros g_sumexp
    cudaStreamWaitEvent(s1, evEctx, 0);
    k_pgen<<<16, 256, 0, s1>>>(gen_W, gen_b, ctrl, out);
    cudaEventRecord(evPgen, s1);

    // main stream: output head (split-K), vocab GEMM, finals
    cudaStreamWaitEvent(0, evDec, 0);
    k_outh<<<dim3(16, 4, 2), 256>>>(outh_W, outh_b, ctrl);
    cudaStreamWaitEvent(0, evPgen, 0);   // sumexp zeroed before outv atomics
    k_outv_mma<<<(V + 63) / 64, 256, MMA_DSMEM>>>(outv_W, outv_b, out);
    k_pfinal<<<dim3((VP / 4 + 255) / 256, B), 256>>>(out);
    k_scatter<<<B, 512>>>(fiv, out);

    cudaEventDestroy(evGates);
    cudaEventDestroy(evDec);
    cudaEventDestroy(evEctx);
    cudaEventDestroy(evPgen);
    cudaStreamDestroy(s1);
}